// round 4
// baseline (speedup 1.0000x reference)
#include <cuda_runtime.h>
#include <cuda_bf16.h>

#define N_PROP 128
#define N_GRIDP 216
#define G_TOT  27648
#define N_KEY  4096
#define C_FEAT 128
#define NS     16
#define K_RED  27648
#define KSPLIT 36
#define KCHUNK 768

typedef unsigned long long ull;

// ---------------- scratch ----------------
static __device__ float  d_grid[G_TOT * 3];
static __device__ float2 d_A[2][N_KEY * 32];
static __device__ int    d_idx[2][G_TOT * NS];
static __device__ float  d_perm[N_PROP * K_RED];
static __device__ float  d_partial[KSPLIT][N_PROP * 256];
static __device__ float  d_hbuf[N_PROP * 256];
static __device__ float  d_w2t[256 * 256];

// ---------------- f32x2 helpers ----------------
__device__ __forceinline__ ull pack2(float x, float y) {
    ull r;
    asm("mov.b64 %0, {%1, %2};" : "=l"(r) : "f"(x), "f"(y));
    return r;
}
__device__ __forceinline__ ull splat2(float x) {
    ull r;
    asm("mov.b64 %0, {%1, %1};" : "=l"(r) : "f"(x));
    return r;
}
__device__ __forceinline__ void fma2(ull& acc, ull a, ull b) {
    asm("fma.rn.f32x2 %0, %1, %2, %0;" : "+l"(acc) : "l"(a), "l"(b));
}
__device__ __forceinline__ float2 unpack2(ull v) {
    float lo, hi;
    asm("mov.b64 {%0, %1}, %2;" : "=f"(lo), "=f"(hi) : "l"(v));
    return make_float2(lo, hi);
}
__device__ __forceinline__ ull d2u(double d) { return __double_as_longlong(d); }

// ---------------- k1: grid points ----------------
__global__ void k_grid(const float* __restrict__ wlh, const float* __restrict__ center,
                       const float* __restrict__ yaw, const float* __restrict__ u)
{
    int g = blockIdx.x * 256 + threadIdx.x;
    if (g >= G_TOT) return;
    int ni = g / N_GRIDP;
    float gx = u[g * 3 + 0] * wlh[ni * 3 + 0];
    float gy = u[g * 3 + 1] * wlh[ni * 3 + 1];
    float gz = u[g * 3 + 2] * wlh[ni * 3 + 2];
    float yv = yaw[ni];
    float c = cosf(yv), s = sinf(yv);
    float rx = c * gx - s * gy;
    float ry = s * gx + c * gy;
    d_grid[g * 3 + 0] = rx + center[ni * 3 + 0];
    d_grid[g * 3 + 1] = ry + center[ni * 3 + 1];
    d_grid[g * 3 + 2] = gz + center[ni * 3 + 2];
}

// ---------------- k2: per-keypoint A = kp.w1[:3] + kf.w1[3:] ----------------
__global__ void __launch_bounds__(256) k_A(const float* __restrict__ kp, const float* __restrict__ kf,
                                           const float* __restrict__ w1_0, const float* __restrict__ w1_1)
{
    __shared__ float w1s[64 * 131];
    const float* w1 = blockIdx.y ? w1_1 : w1_0;
    int tid = threadIdx.y * 32 + threadIdx.x;
    for (int i = tid; i < 64 * 131; i += 256) w1s[i] = w1[i];
    __syncthreads();

    int l = threadIdx.x;
    int kbase = blockIdx.x * 256;
    for (int t = 0; t < 32; t++) {
        int k = kbase + t * 8 + threadIdx.y;
        float kx = kp[k * 3 + 0], ky = kp[k * 3 + 1], kz = kp[k * 3 + 2];
        float a0 = w1s[l * 131 + 0] * kx + w1s[l * 131 + 1] * ky + w1s[l * 131 + 2] * kz;
        float a1 = w1s[(l + 32) * 131 + 0] * kx + w1s[(l + 32) * 131 + 1] * ky + w1s[(l + 32) * 131 + 2] * kz;
#pragma unroll 4
        for (int c = 0; c < C_FEAT; c++) {
            float f = kf[c * N_KEY + k];
            a0 = fmaf(f, w1s[l * 131 + 3 + c], a0);
            a1 = fmaf(f, w1s[(l + 32) * 131 + 3 + c], a1);
        }
        d_A[blockIdx.y][k * 32 + l] = make_float2(a0, a1);
    }
}

// ---------------- k3: ball query, float4 smem, fma distance ----------------
__global__ void __launch_bounds__(256) k_ball(const float* __restrict__ kp)
{
    extern __shared__ float4 kpt[];   // 4096 * 16B = 64KB dynamic
    for (int i = threadIdx.x; i < N_KEY; i += 256) {
        float kx = kp[i * 3 + 0], ky = kp[i * 3 + 1], kz = kp[i * 3 + 2];
        kpt[i] = make_float4(kx, ky, kz, kx * kx + ky * ky + kz * kz);
    }
    __syncthreads();

    int g = blockIdx.x * 256 + threadIdx.x;
    float gx = d_grid[g * 3 + 0], gy = d_grid[g * 3 + 1], gz = d_grid[g * 3 + 2];
    float gs = gx * gx + gy * gy + gz * gz;
    float m2x = -2.f * gx, m2y = -2.f * gy, m2z = -2.f * gz;

    int c0 = 0, c1 = 0, f0 = 0, f1 = 0;
    int* o0 = &d_idx[0][g * NS];
    int* o1 = &d_idx[1][g * NS];

#pragma unroll 4
    for (int k = 0; k < N_KEY; k++) {
        float4 v = kpt[k];
        float d2 = fmaf(m2x, v.x, fmaf(m2y, v.y, fmaf(m2z, v.z, gs + v.w)));
        if (d2 < 2.56f) {
            if (c1 < NS) { if (c1 == 0) f1 = k; o1[c1++] = k; }
            if (d2 < 0.64f) {
                if (c0 == 0) f0 = k;
                o0[c0++] = k;
                if (c0 == NS) break;   // r0 hits subset of r1 hits -> c1 full too
            }
        }
    }
    for (int n = c1; n < NS; n++) o1[n] = f1;
    for (int n = c0; n < NS; n++) o0[n] = f0;
}

// ---------------- k4: branch MLP + maxpool, warp per grid point, 4-sample groups --
__global__ void __launch_bounds__(256, 1) k_branch(
    const float* __restrict__ w1_0, const float* __restrict__ g1_0, const float* __restrict__ b1_0,
    const float* __restrict__ w2_0, const float* __restrict__ g2_0, const float* __restrict__ b2_0,
    const float* __restrict__ w1_1, const float* __restrict__ g1_1, const float* __restrict__ b1_1,
    const float* __restrict__ w2_1, const float* __restrict__ g2_1, const float* __restrict__ b2_1)
{
    const int b = blockIdx.y;
    const float* w1 = b ? w1_1 : w1_0;
    const float* g1 = b ? g1_1 : g1_0;
    const float* b1 = b ? b1_1 : b1_0;
    const float* w2 = b ? w2_1 : w2_0;
    const float* g2 = b ? g2_1 : g2_0;
    const float* b2 = b ? b2_1 : b2_0;

    const int lane = threadIdx.x & 31;
    const int warp = threadIdx.x >> 5;

    __shared__ __align__(16) float hbuf[8][4 * 64];   // per warp: 4 samples x 64 ch
    float* hb = hbuf[warp];

    // w2 rows for outputs o=lane and o=lane+32, as f32x2 pairs (c, c+1)
    ull w2lo[32], w2hi[32];
    const double2* w2d = (const double2*)w2;          // 16 double2 per 64-float row
#pragma unroll
    for (int jj = 0; jj < 16; jj++) {
        double2 vlo = w2d[lane * 16 + jj];
        double2 vhi = w2d[(lane + 32) * 16 + jj];
        w2lo[2 * jj] = d2u(vlo.x); w2lo[2 * jj + 1] = d2u(vlo.y);
        w2hi[2 * jj] = d2u(vhi.x); w2hi[2 * jj + 1] = d2u(vhi.y);
    }
    const float g1lo = g1[lane], g1hi = g1[lane + 32];
    const float b1lo = b1[lane], b1hi = b1[lane + 32];
    const float g2lo = g2[lane], g2hi = g2[lane + 32];
    const float b2lo = b2[lane], b2hi = b2[lane + 32];
    const float w1x0 = w1[lane * 131 + 0], w1y0 = w1[lane * 131 + 1], w1z0 = w1[lane * 131 + 2];
    const float w1x1 = w1[(lane + 32) * 131 + 0], w1y1 = w1[(lane + 32) * 131 + 1], w1z1 = w1[(lane + 32) * 131 + 2];

    const float2* __restrict__ A2 = d_A[b];
    const int*    __restrict__ idxp = d_idx[b];

    for (int g = blockIdx.x * 8 + warp; g < G_TOT; g += gridDim.x * 8) {
        float gx = d_grid[g * 3 + 0], gy = d_grid[g * 3 + 1], gz = d_grid[g * 3 + 2];
        float qlo = w1x0 * gx + w1y0 * gy + w1z0 * gz;
        float qhi = w1x1 * gx + w1y1 * gy + w1z1 * gz;
        int kreg = idxp[g * NS + (lane & 15)];
        float mxA = -1e30f, mxB = -1e30f;

#pragma unroll 1
        for (int n0 = 0; n0 < NS; n0 += 4) {
            // gather 4 samples' A rows (independent LDGs -> MLP=4)
            int k0 = __shfl_sync(0xffffffffu, kreg, n0 + 0);
            int k1 = __shfl_sync(0xffffffffu, kreg, n0 + 1);
            int k2 = __shfl_sync(0xffffffffu, kreg, n0 + 2);
            int k3 = __shfl_sync(0xffffffffu, kreg, n0 + 3);
            float2 av0 = A2[k0 * 32 + lane];
            float2 av1 = A2[k1 * 32 + lane];
            float2 av2 = A2[k2 * 32 + lane];
            float2 av3 = A2[k3 * 32 + lane];
            hb[0 * 64 + lane]      = fmaxf(fmaf(g1lo, av0.x - qlo, b1lo), 0.f);
            hb[0 * 64 + 32 + lane] = fmaxf(fmaf(g1hi, av0.y - qhi, b1hi), 0.f);
            hb[1 * 64 + lane]      = fmaxf(fmaf(g1lo, av1.x - qlo, b1lo), 0.f);
            hb[1 * 64 + 32 + lane] = fmaxf(fmaf(g1hi, av1.y - qhi, b1hi), 0.f);
            hb[2 * 64 + lane]      = fmaxf(fmaf(g1lo, av2.x - qlo, b1lo), 0.f);
            hb[2 * 64 + 32 + lane] = fmaxf(fmaf(g1hi, av2.y - qhi, b1hi), 0.f);
            hb[3 * 64 + lane]      = fmaxf(fmaf(g1lo, av3.x - qlo, b1lo), 0.f);
            hb[3 * 64 + 32 + lane] = fmaxf(fmaf(g1hi, av3.y - qhi, b1hi), 0.f);
            __syncwarp();

            ull aLo0 = 0, aLo1 = 0, aLo2 = 0, aLo3 = 0;
            ull aHi0 = 0, aHi1 = 0, aHi2 = 0, aHi3 = 0;
            const double2* h0 = (const double2*)(hb + 0 * 64);
            const double2* h1 = (const double2*)(hb + 1 * 64);
            const double2* h2 = (const double2*)(hb + 2 * 64);
            const double2* h3 = (const double2*)(hb + 3 * 64);
#pragma unroll
            for (int jj = 0; jj < 16; jj++) {
                ull wl0 = w2lo[2 * jj], wl1 = w2lo[2 * jj + 1];
                ull wh0 = w2hi[2 * jj], wh1 = w2hi[2 * jj + 1];
                double2 d0 = h0[jj];
                fma2(aLo0, d2u(d0.x), wl0); fma2(aLo0, d2u(d0.y), wl1);
                fma2(aHi0, d2u(d0.x), wh0); fma2(aHi0, d2u(d0.y), wh1);
                double2 d1 = h1[jj];
                fma2(aLo1, d2u(d1.x), wl0); fma2(aLo1, d2u(d1.y), wl1);
                fma2(aHi1, d2u(d1.x), wh0); fma2(aHi1, d2u(d1.y), wh1);
                double2 d2v = h2[jj];
                fma2(aLo2, d2u(d2v.x), wl0); fma2(aLo2, d2u(d2v.y), wl1);
                fma2(aHi2, d2u(d2v.x), wh0); fma2(aHi2, d2u(d2v.y), wh1);
                double2 d3 = h3[jj];
                fma2(aLo3, d2u(d3.x), wl0); fma2(aLo3, d2u(d3.y), wl1);
                fma2(aHi3, d2u(d3.x), wh0); fma2(aHi3, d2u(d3.y), wh1);
            }
            __syncwarp();

            float2 p;
            p = unpack2(aLo0); mxA = fmaxf(mxA, fmaf(g2lo, p.x + p.y, b2lo));
            p = unpack2(aLo1); mxA = fmaxf(mxA, fmaf(g2lo, p.x + p.y, b2lo));
            p = unpack2(aLo2); mxA = fmaxf(mxA, fmaf(g2lo, p.x + p.y, b2lo));
            p = unpack2(aLo3); mxA = fmaxf(mxA, fmaf(g2lo, p.x + p.y, b2lo));
            p = unpack2(aHi0); mxB = fmaxf(mxB, fmaf(g2hi, p.x + p.y, b2hi));
            p = unpack2(aHi1); mxB = fmaxf(mxB, fmaf(g2hi, p.x + p.y, b2hi));
            p = unpack2(aHi2); mxB = fmaxf(mxB, fmaf(g2hi, p.x + p.y, b2hi));
            p = unpack2(aHi3); mxB = fmaxf(mxB, fmaf(g2hi, p.x + p.y, b2hi));
        }
        // scatter into permuted red_in layout: flat = mi*16384 + cp*128 + ni
        int ni = g / N_GRIDP, mi = g % N_GRIDP;
        int cpA = b * 64 + lane;
        d_perm[mi * 16384 + cpA * 128 + ni] = fmaxf(mxA, 0.f);
        d_perm[mi * 16384 + (cpA + 32) * 128 + ni] = fmaxf(mxB, 0.f);
    }
}

// ---------------- k5: reduction GEMM layer1, split-K=36, f32x2 ----------------
__global__ void __launch_bounds__(256) k_red1(const float* __restrict__ W)
{
    __shared__ __align__(16) float As[32][132];   // [kk][i], rows 16B-aligned
    __shared__ __align__(16) float Bs[32][68];    // [kk][o]
    const int ob = blockIdx.x * 64;
    const int kbase = blockIdx.y * KCHUNK;
    const int tid = threadIdx.x;
    const int tx = tid & 15, ty = tid >> 4;

    ull acc[4][4];
#pragma unroll
    for (int r = 0; r < 4; r++)
#pragma unroll
        for (int c = 0; c < 4; c++) acc[r][c] = 0;

    for (int kc = 0; kc < KCHUNK; kc += 32) {
        int k0 = kbase + kc;
#pragma unroll
        for (int r = 0; r < 16; r++) {
            int e = tid + 256 * r;
            int i = e >> 5, kk = e & 31;
            As[kk][i] = d_perm[i * K_RED + k0 + kk];
        }
#pragma unroll
        for (int r = 0; r < 8; r++) {
            int e = tid + 256 * r;
            int o = e >> 5, kk = e & 31;
            Bs[kk][o] = W[(ob + o) * K_RED + k0 + kk];
        }
        __syncthreads();
#pragma unroll
        for (int kk = 0; kk < 32; kk++) {
            double2 a01 = *(const double2*)&As[kk][ty * 8];
            double2 a23 = *(const double2*)&As[kk][ty * 8 + 4];
            float4 bv = *(const float4*)&Bs[kk][tx * 4];
            ull ap0 = d2u(a01.x), ap1 = d2u(a01.y), ap2 = d2u(a23.x), ap3 = d2u(a23.y);
            ull b0 = splat2(bv.x), b1 = splat2(bv.y), b2 = splat2(bv.z), b3 = splat2(bv.w);
            fma2(acc[0][0], ap0, b0); fma2(acc[0][1], ap0, b1); fma2(acc[0][2], ap0, b2); fma2(acc[0][3], ap0, b3);
            fma2(acc[1][0], ap1, b0); fma2(acc[1][1], ap1, b1); fma2(acc[1][2], ap1, b2); fma2(acc[1][3], ap1, b3);
            fma2(acc[2][0], ap2, b0); fma2(acc[2][1], ap2, b1); fma2(acc[2][2], ap2, b2); fma2(acc[2][3], ap2, b3);
            fma2(acc[3][0], ap3, b0); fma2(acc[3][1], ap3, b1); fma2(acc[3][2], ap3, b2); fma2(acc[3][3], ap3, b3);
        }
        __syncthreads();
    }
    float* outp = d_partial[blockIdx.y];
#pragma unroll
    for (int rp = 0; rp < 4; rp++)
#pragma unroll
        for (int c = 0; c < 4; c++) {
            float2 v = unpack2(acc[rp][c]);
            outp[(ty * 8 + 2 * rp) * 256 + ob + tx * 4 + c] = v.x;
            outp[(ty * 8 + 2 * rp + 1) * 256 + ob + tx * 4 + c] = v.y;
        }
}

// ---------------- k6: partial reduce + bias + relu ----------------
__global__ void k_redfin(const float* __restrict__ b1)
{
    int t = blockIdx.x * 256 + threadIdx.x;     // 32768 total
    float s = b1[t & 255];
#pragma unroll
    for (int ks = 0; ks < KSPLIT; ks++) s += d_partial[ks][t];
    d_hbuf[t] = fmaxf(s, 0.f);
}

// ---------------- k6b: transpose W2 ----------------
__global__ void k_w2t(const float* __restrict__ W2)
{
    __shared__ float tbuf[32][33];
    int x = blockIdx.x * 32 + threadIdx.x;
    int y0 = blockIdx.y * 32;
#pragma unroll
    for (int r = threadIdx.y; r < 32; r += 8)
        tbuf[r][threadIdx.x] = W2[(y0 + r) * 256 + x];
    __syncthreads();
    int xo = blockIdx.y * 32 + threadIdx.x;
#pragma unroll
    for (int r = threadIdx.y; r < 32; r += 8)
        d_w2t[(blockIdx.x * 32 + r) * 256 + xo] = tbuf[threadIdx.x][r];
}

// ---------------- k7: layer2 256x256 + relu (coalesced via W2^T) -------------
__global__ void __launch_bounds__(256) k_red2(const float* __restrict__ b2, float* __restrict__ out)
{
    __shared__ float hs[256];
    int i = blockIdx.x;
    hs[threadIdx.x] = d_hbuf[i * 256 + threadIdx.x];
    __syncthreads();
    int o = threadIdx.x;
    float s = b2[o];
#pragma unroll 8
    for (int c = 0; c < 256; c++) s = fmaf(hs[c], d_w2t[c * 256 + o], s);
    out[i * 256 + o] = fmaxf(s, 0.f);
}

// ---------------- launch ----------------
extern "C" void kernel_launch(void* const* d_in, const int* in_sizes, int n_in,
                              void* d_out, int out_size)
{
    const float* wlh    = (const float*)d_in[0];
    const float* center = (const float*)d_in[1];
    const float* yaw    = (const float*)d_in[2];
    const float* u      = (const float*)d_in[3];
    const float* kp     = (const float*)d_in[4];
    const float* kf     = (const float*)d_in[5];
    const float* pn0_w1 = (const float*)d_in[6];
    const float* pn0_g1 = (const float*)d_in[7];
    const float* pn0_b1 = (const float*)d_in[8];
    const float* pn0_w2 = (const float*)d_in[9];
    const float* pn0_g2 = (const float*)d_in[10];
    const float* pn0_b2 = (const float*)d_in[11];
    const float* pn1_w1 = (const float*)d_in[12];
    const float* pn1_g1 = (const float*)d_in[13];
    const float* pn1_b1 = (const float*)d_in[14];
    const float* pn1_w2 = (const float*)d_in[15];
    const float* pn1_g2 = (const float*)d_in[16];
    const float* pn1_b2 = (const float*)d_in[17];
    const float* red_w1 = (const float*)d_in[18];
    const float* red_b1 = (const float*)d_in[19];
    const float* red_w2 = (const float*)d_in[20];
    const float* red_b2 = (const float*)d_in[21];
    float* out = (float*)d_out;

    cudaFuncSetAttribute(k_ball, cudaFuncAttributeMaxDynamicSharedMemorySize, 65536);

    k_grid<<<(G_TOT + 255) / 256, 256>>>(wlh, center, yaw, u);
    k_A<<<dim3(16, 2), dim3(32, 8)>>>(kp, kf, pn0_w1, pn1_w1);
    k_ball<<<G_TOT / 256, 256, 65536>>>(kp);
    k_w2t<<<dim3(8, 8), dim3(32, 8)>>>(red_w2);
    k_branch<<<dim3(74, 2), 256>>>(pn0_w1, pn0_g1, pn0_b1, pn0_w2, pn0_g2, pn0_b2,
                                   pn1_w1, pn1_g1, pn1_b1, pn1_w2, pn1_g2, pn1_b2);
    k_red1<<<dim3(4, KSPLIT), 256>>>(red_w1);
    k_redfin<<<128, 256>>>(red_b1);
    k_red2<<<128, 256>>>(red_b2, out);
}

// round 5
// speedup vs baseline: 1.8816x; 1.8816x over previous
#include <cuda_runtime.h>
#include <cuda_bf16.h>

#define N_PROP 128
#define N_GRIDP 216
#define G_TOT  27648
#define N_KEY  4096
#define C_FEAT 128
#define NS     16
#define K_RED  27648
#define KSPLIT 36
#define KCHUNK 768

typedef unsigned long long ull;

// ---------------- scratch ----------------
static __device__ float  d_grid[G_TOT * 3];
static __device__ float2 d_A[2][N_KEY * 32];
static __device__ int    d_idx[2][G_TOT * NS];
static __device__ float  d_perm[N_PROP * K_RED];
static __device__ float  d_partial[KSPLIT][N_PROP * 256];
static __device__ float  d_hbuf[N_PROP * 256];
static __device__ float  d_w2t[256 * 256];

// ---------------- f32x2 helpers ----------------
__device__ __forceinline__ ull splat2(float x) {
    ull r;
    asm("mov.b64 %0, {%1, %1};" : "=l"(r) : "f"(x));
    return r;
}
__device__ __forceinline__ void fma2(ull& acc, ull a, ull b) {
    asm("fma.rn.f32x2 %0, %1, %2, %0;" : "+l"(acc) : "l"(a), "l"(b));
}
__device__ __forceinline__ float2 unpack2(ull v) {
    float lo, hi;
    asm("mov.b64 {%0, %1}, %2;" : "=f"(lo), "=f"(hi) : "l"(v));
    return make_float2(lo, hi);
}
__device__ __forceinline__ ull d2u(double d) { return __double_as_longlong(d); }

// ---------------- k1: grid points ----------------
__global__ void k_grid(const float* __restrict__ wlh, const float* __restrict__ center,
                       const float* __restrict__ yaw, const float* __restrict__ u)
{
    int g = blockIdx.x * 256 + threadIdx.x;
    if (g >= G_TOT) return;
    int ni = g / N_GRIDP;
    float gx = u[g * 3 + 0] * wlh[ni * 3 + 0];
    float gy = u[g * 3 + 1] * wlh[ni * 3 + 1];
    float gz = u[g * 3 + 2] * wlh[ni * 3 + 2];
    float yv = yaw[ni];
    float c = cosf(yv), s = sinf(yv);
    float rx = c * gx - s * gy;
    float ry = s * gx + c * gy;
    d_grid[g * 3 + 0] = rx + center[ni * 3 + 0];
    d_grid[g * 3 + 1] = ry + center[ni * 3 + 1];
    d_grid[g * 3 + 2] = gz + center[ni * 3 + 2];
}

// ---------------- k2: per-keypoint A = kp.w1[:3] + kf.w1[3:] ----------------
// grid (64, 2): 64 keypoints per block
__global__ void __launch_bounds__(256) k_A(const float* __restrict__ kp, const float* __restrict__ kf,
                                           const float* __restrict__ w1_0, const float* __restrict__ w1_1)
{
    __shared__ float w1s[64 * 131];
    const float* w1 = blockIdx.y ? w1_1 : w1_0;
    int tid = threadIdx.y * 32 + threadIdx.x;
    for (int i = tid; i < 64 * 131; i += 256) w1s[i] = w1[i];
    __syncthreads();

    int l = threadIdx.x;
    int kbase = blockIdx.x * 64;
#pragma unroll 1
    for (int t = 0; t < 8; t++) {
        int k = kbase + t * 8 + threadIdx.y;
        float kx = kp[k * 3 + 0], ky = kp[k * 3 + 1], kz = kp[k * 3 + 2];
        float a0 = w1s[l * 131 + 0] * kx + w1s[l * 131 + 1] * ky + w1s[l * 131 + 2] * kz;
        float a1 = w1s[(l + 32) * 131 + 0] * kx + w1s[(l + 32) * 131 + 1] * ky + w1s[(l + 32) * 131 + 2] * kz;
#pragma unroll 4
        for (int c = 0; c < C_FEAT; c++) {
            float f = kf[c * N_KEY + k];
            a0 = fmaf(f, w1s[l * 131 + 3 + c], a0);
            a1 = fmaf(f, w1s[(l + 32) * 131 + 3 + c], a1);
        }
        d_A[blockIdx.y][k * 32 + l] = make_float2(a0, a1);
    }
}

// ---------------- k3: ball query, float4 smem, fma distance ----------------
__global__ void __launch_bounds__(256) k_ball(const float* __restrict__ kp)
{
    extern __shared__ float4 kpt[];   // 4096 * 16B = 64KB dynamic
    for (int i = threadIdx.x; i < N_KEY; i += 256) {
        float kx = kp[i * 3 + 0], ky = kp[i * 3 + 1], kz = kp[i * 3 + 2];
        kpt[i] = make_float4(kx, ky, kz, kx * kx + ky * ky + kz * kz);
    }
    __syncthreads();

    int g = blockIdx.x * 256 + threadIdx.x;
    float gx = d_grid[g * 3 + 0], gy = d_grid[g * 3 + 1], gz = d_grid[g * 3 + 2];
    float gs = gx * gx + gy * gy + gz * gz;
    float m2x = -2.f * gx, m2y = -2.f * gy, m2z = -2.f * gz;

    int c0 = 0, c1 = 0, f0 = 0, f1 = 0;
    int* o0 = &d_idx[0][g * NS];
    int* o1 = &d_idx[1][g * NS];

#pragma unroll 4
    for (int k = 0; k < N_KEY; k++) {
        float4 v = kpt[k];
        float d2 = fmaf(m2x, v.x, fmaf(m2y, v.y, fmaf(m2z, v.z, gs + v.w)));
        if (d2 < 2.56f) {
            if (c1 < NS) { if (c1 == 0) f1 = k; o1[c1++] = k; }
            if (d2 < 0.64f) {
                if (c0 == 0) f0 = k;
                o0[c0++] = k;
                if (c0 == NS) break;   // r0 hits subset of r1 hits -> c1 full too
            }
        }
    }
    for (int n = c1; n < NS; n++) o1[n] = f1;
    for (int n = c0; n < NS; n++) o0[n] = f0;
}

// ---------------- k4: branch MLP + maxpool, warp per grid point ----------------
// Single-sample pipeline (register-safe), double-buffered hb (1 syncwarp/sample),
// prefetched A2 gather.
__global__ void __launch_bounds__(256, 1) k_branch(
    const float* __restrict__ w1_0, const float* __restrict__ g1_0, const float* __restrict__ b1_0,
    const float* __restrict__ w2_0, const float* __restrict__ g2_0, const float* __restrict__ b2_0,
    const float* __restrict__ w1_1, const float* __restrict__ g1_1, const float* __restrict__ b1_1,
    const float* __restrict__ w2_1, const float* __restrict__ g2_1, const float* __restrict__ b2_1)
{
    const int b = blockIdx.y;
    const float* w1 = b ? w1_1 : w1_0;
    const float* g1 = b ? g1_1 : g1_0;
    const float* b1 = b ? b1_1 : b1_0;
    const float* w2 = b ? w2_1 : w2_0;
    const float* g2 = b ? g2_1 : g2_0;
    const float* b2 = b ? b2_1 : b2_0;

    const int lane = threadIdx.x & 31;
    const int warp = threadIdx.x >> 5;

    __shared__ __align__(16) float hbuf[8][2][64];   // per warp: 2 buffers x 64 ch

    // w2 rows for outputs o=lane, o=lane+32, as f32x2 pairs (c, c+1)
    ull w2lo[32], w2hi[32];
    const double2* w2d = (const double2*)w2;
#pragma unroll
    for (int jj = 0; jj < 16; jj++) {
        double2 vlo = w2d[lane * 16 + jj];
        double2 vhi = w2d[(lane + 32) * 16 + jj];
        w2lo[2 * jj] = d2u(vlo.x); w2lo[2 * jj + 1] = d2u(vlo.y);
        w2hi[2 * jj] = d2u(vhi.x); w2hi[2 * jj + 1] = d2u(vhi.y);
    }
    const float g1lo = g1[lane], g1hi = g1[lane + 32];
    const float b1lo = b1[lane], b1hi = b1[lane + 32];
    const float g2lo = g2[lane], g2hi = g2[lane + 32];
    const float b2lo = b2[lane], b2hi = b2[lane + 32];
    const float w1x0 = w1[lane * 131 + 0], w1y0 = w1[lane * 131 + 1], w1z0 = w1[lane * 131 + 2];
    const float w1x1 = w1[(lane + 32) * 131 + 0], w1y1 = w1[(lane + 32) * 131 + 1], w1z1 = w1[(lane + 32) * 131 + 2];

    const float2* __restrict__ A2 = d_A[b];
    const int*    __restrict__ idxp = d_idx[b];

    for (int g = blockIdx.x * 8 + warp; g < G_TOT; g += gridDim.x * 8) {
        float gx = d_grid[g * 3 + 0], gy = d_grid[g * 3 + 1], gz = d_grid[g * 3 + 2];
        float qlo = w1x0 * gx + w1y0 * gy + w1z0 * gz;
        float qhi = w1x1 * gx + w1y1 * gy + w1z1 * gz;
        int kreg = idxp[g * NS + (lane & 15)];
        float mxA = -1e30f, mxB = -1e30f;

        // prefetch sample 0
        int kcur = __shfl_sync(0xffffffffu, kreg, 0);
        float2 av = A2[kcur * 32 + lane];

#pragma unroll 1
        for (int n = 0; n < NS; n++) {
            // prefetch next sample's A row (overlaps with this sample's compute)
            int knext = __shfl_sync(0xffffffffu, kreg, (n + 1) & 15);
            float2 avn = A2[knext * 32 + lane];

            float* hb = hbuf[warp][n & 1];
            hb[lane]      = fmaxf(fmaf(g1lo, av.x - qlo, b1lo), 0.f);
            hb[lane + 32] = fmaxf(fmaf(g1hi, av.y - qhi, b1hi), 0.f);
            __syncwarp();

            ull a0 = 0, a1 = 0, c0 = 0, c1 = 0;
            const double2* h2 = (const double2*)hb;
#pragma unroll
            for (int jj = 0; jj < 8; jj++) {
                double2 v0 = h2[2 * jj];
                double2 v1 = h2[2 * jj + 1];
                fma2(a0, d2u(v0.x), w2lo[4 * jj + 0]);
                fma2(a1, d2u(v0.y), w2lo[4 * jj + 1]);
                fma2(c0, d2u(v0.x), w2hi[4 * jj + 0]);
                fma2(c1, d2u(v0.y), w2hi[4 * jj + 1]);
                fma2(a0, d2u(v1.x), w2lo[4 * jj + 2]);
                fma2(a1, d2u(v1.y), w2lo[4 * jj + 3]);
                fma2(c0, d2u(v1.x), w2hi[4 * jj + 2]);
                fma2(c1, d2u(v1.y), w2hi[4 * jj + 3]);
            }
            float2 pa0 = unpack2(a0), pa1 = unpack2(a1);
            float2 pc0 = unpack2(c0), pc1 = unpack2(c1);
            float dotA = (pa0.x + pa0.y) + (pa1.x + pa1.y);
            float dotB = (pc0.x + pc0.y) + (pc1.x + pc1.y);
            mxA = fmaxf(mxA, fmaf(g2lo, dotA, b2lo));
            mxB = fmaxf(mxB, fmaf(g2hi, dotB, b2hi));
            av = avn;
        }
        // scatter into permuted red_in layout: flat = mi*16384 + cp*128 + ni
        int ni = g / N_GRIDP, mi = g % N_GRIDP;
        int cpA = b * 64 + lane;
        d_perm[mi * 16384 + cpA * 128 + ni] = fmaxf(mxA, 0.f);
        d_perm[mi * 16384 + (cpA + 32) * 128 + ni] = fmaxf(mxB, 0.f);
    }
}

// ---------------- k5: reduction GEMM layer1, split-K=36, f32x2 ----------------
__global__ void __launch_bounds__(256) k_red1(const float* __restrict__ W)
{
    __shared__ __align__(16) float As[32][132];
    __shared__ __align__(16) float Bs[32][68];
    const int ob = blockIdx.x * 64;
    const int kbase = blockIdx.y * KCHUNK;
    const int tid = threadIdx.x;
    const int tx = tid & 15, ty = tid >> 4;

    ull acc[4][4];
#pragma unroll
    for (int r = 0; r < 4; r++)
#pragma unroll
        for (int c = 0; c < 4; c++) acc[r][c] = 0;

    for (int kc = 0; kc < KCHUNK; kc += 32) {
        int k0 = kbase + kc;
#pragma unroll
        for (int r = 0; r < 16; r++) {
            int e = tid + 256 * r;
            int i = e >> 5, kk = e & 31;
            As[kk][i] = d_perm[i * K_RED + k0 + kk];
        }
#pragma unroll
        for (int r = 0; r < 8; r++) {
            int e = tid + 256 * r;
            int o = e >> 5, kk = e & 31;
            Bs[kk][o] = W[(ob + o) * K_RED + k0 + kk];
        }
        __syncthreads();
#pragma unroll
        for (int kk = 0; kk < 32; kk++) {
            double2 a01 = *(const double2*)&As[kk][ty * 8];
            double2 a23 = *(const double2*)&As[kk][ty * 8 + 4];
            float4 bv = *(const float4*)&Bs[kk][tx * 4];
            ull ap0 = d2u(a01.x), ap1 = d2u(a01.y), ap2 = d2u(a23.x), ap3 = d2u(a23.y);
            ull b0 = splat2(bv.x), b1 = splat2(bv.y), b2 = splat2(bv.z), b3 = splat2(bv.w);
            fma2(acc[0][0], ap0, b0); fma2(acc[0][1], ap0, b1); fma2(acc[0][2], ap0, b2); fma2(acc[0][3], ap0, b3);
            fma2(acc[1][0], ap1, b0); fma2(acc[1][1], ap1, b1); fma2(acc[1][2], ap1, b2); fma2(acc[1][3], ap1, b3);
            fma2(acc[2][0], ap2, b0); fma2(acc[2][1], ap2, b1); fma2(acc[2][2], ap2, b2); fma2(acc[2][3], ap2, b3);
            fma2(acc[3][0], ap3, b0); fma2(acc[3][1], ap3, b1); fma2(acc[3][2], ap3, b2); fma2(acc[3][3], ap3, b3);
        }
        __syncthreads();
    }
    float* outp = d_partial[blockIdx.y];
#pragma unroll
    for (int rp = 0; rp < 4; rp++)
#pragma unroll
        for (int c = 0; c < 4; c++) {
            float2 v = unpack2(acc[rp][c]);
            outp[(ty * 8 + 2 * rp) * 256 + ob + tx * 4 + c] = v.x;
            outp[(ty * 8 + 2 * rp + 1) * 256 + ob + tx * 4 + c] = v.y;
        }
}

// ---------------- k6: partial reduce + bias + relu ----------------
__global__ void k_redfin(const float* __restrict__ b1)
{
    int t = blockIdx.x * 256 + threadIdx.x;
    float s = b1[t & 255];
#pragma unroll
    for (int ks = 0; ks < KSPLIT; ks++) s += d_partial[ks][t];
    d_hbuf[t] = fmaxf(s, 0.f);
}

// ---------------- k6b: transpose W2 ----------------
__global__ void k_w2t(const float* __restrict__ W2)
{
    __shared__ float tbuf[32][33];
    int x = blockIdx.x * 32 + threadIdx.x;
    int y0 = blockIdx.y * 32;
#pragma unroll
    for (int r = threadIdx.y; r < 32; r += 8)
        tbuf[r][threadIdx.x] = W2[(y0 + r) * 256 + x];
    __syncthreads();
    int xo = blockIdx.y * 32 + threadIdx.x;
#pragma unroll
    for (int r = threadIdx.y; r < 32; r += 8)
        d_w2t[(blockIdx.x * 32 + r) * 256 + xo] = tbuf[threadIdx.x][r];
}

// ---------------- k7: layer2 256x256 + relu (coalesced via W2^T) -------------
__global__ void __launch_bounds__(256) k_red2(const float* __restrict__ b2, float* __restrict__ out)
{
    __shared__ float hs[256];
    int i = blockIdx.x;
    hs[threadIdx.x] = d_hbuf[i * 256 + threadIdx.x];
    __syncthreads();
    int o = threadIdx.x;
    float s = b2[o];
#pragma unroll 8
    for (int c = 0; c < 256; c++) s = fmaf(hs[c], d_w2t[c * 256 + o], s);
    out[i * 256 + o] = fmaxf(s, 0.f);
}

// ---------------- launch ----------------
extern "C" void kernel_launch(void* const* d_in, const int* in_sizes, int n_in,
                              void* d_out, int out_size)
{
    const float* wlh    = (const float*)d_in[0];
    const float* center = (const float*)d_in[1];
    const float* yaw    = (const float*)d_in[2];
    const float* u      = (const float*)d_in[3];
    const float* kp     = (const float*)d_in[4];
    const float* kf     = (const float*)d_in[5];
    const float* pn0_w1 = (const float*)d_in[6];
    const float* pn0_g1 = (const float*)d_in[7];
    const float* pn0_b1 = (const float*)d_in[8];
    const float* pn0_w2 = (const float*)d_in[9];
    const float* pn0_g2 = (const float*)d_in[10];
    const float* pn0_b2 = (const float*)d_in[11];
    const float* pn1_w1 = (const float*)d_in[12];
    const float* pn1_g1 = (const float*)d_in[13];
    const float* pn1_b1 = (const float*)d_in[14];
    const float* pn1_w2 = (const float*)d_in[15];
    const float* pn1_g2 = (const float*)d_in[16];
    const float* pn1_b2 = (const float*)d_in[17];
    const float* red_w1 = (const float*)d_in[18];
    const float* red_b1 = (const float*)d_in[19];
    const float* red_w2 = (const float*)d_in[20];
    const float* red_b2 = (const float*)d_in[21];
    float* out = (float*)d_out;

    cudaFuncSetAttribute(k_ball, cudaFuncAttributeMaxDynamicSharedMemorySize, 65536);

    k_grid<<<(G_TOT + 255) / 256, 256>>>(wlh, center, yaw, u);
    k_A<<<dim3(64, 2), dim3(32, 8)>>>(kp, kf, pn0_w1, pn1_w1);
    k_ball<<<G_TOT / 256, 256, 65536>>>(kp);
    k_w2t<<<dim3(8, 8), dim3(32, 8)>>>(red_w2);
    k_branch<<<dim3(74, 2), 256>>>(pn0_w1, pn0_g1, pn0_b1, pn0_w2, pn0_g2, pn0_b2,
                                   pn1_w1, pn1_g1, pn1_b1, pn1_w2, pn1_g2, pn1_b2);
    k_red1<<<dim3(4, KSPLIT), 256>>>(red_w1);
    k_redfin<<<128, 256>>>(red_b1);
    k_red2<<<128, 256>>>(red_b2, out);
}

// round 6
// speedup vs baseline: 2.1614x; 1.1487x over previous
#include <cuda_runtime.h>
#include <cuda_bf16.h>

#define N_PROP 128
#define N_GRIDP 216
#define G_TOT  27648
#define N_KEY  4096
#define C_FEAT 128
#define NS     16
#define K_RED  27648
#define KSPLIT 36
#define KCHUNK 768
#define NCHUNK 6912              // 2 * 27648 / 8

typedef unsigned long long ull;

// ---------------- scratch ----------------
static __device__ float  d_grid[G_TOT * 3];
static __device__ float2 d_A[2][N_KEY * 32];
static __device__ int    d_idx[2][G_TOT * NS];
static __device__ int    d_cnt[2][G_TOT];
static __device__ float  d_perm[N_PROP * K_RED];
static __device__ float  d_partial[KSPLIT][N_PROP * 256];
static __device__ float  d_hbuf[N_PROP * 256];
static __device__ float  d_w2t[256 * 256];
static __device__ unsigned d_work;

// ---------------- f32x2 helpers ----------------
__device__ __forceinline__ ull splat2(float x) {
    ull r;
    asm("mov.b64 %0, {%1, %1};" : "=l"(r) : "f"(x));
    return r;
}
__device__ __forceinline__ void fma2(ull& acc, ull a, ull b) {
    asm("fma.rn.f32x2 %0, %1, %2, %0;" : "+l"(acc) : "l"(a), "l"(b));
}
__device__ __forceinline__ float2 unpack2(ull v) {
    float lo, hi;
    asm("mov.b64 {%0, %1}, %2;" : "=f"(lo), "=f"(hi) : "l"(v));
    return make_float2(lo, hi);
}
__device__ __forceinline__ ull d2u(double d) { return __double_as_longlong(d); }

// ---------------- k1: grid points (+ work counter reset) ----------------
__global__ void k_grid(const float* __restrict__ wlh, const float* __restrict__ center,
                       const float* __restrict__ yaw, const float* __restrict__ u)
{
    if (blockIdx.x == 0 && threadIdx.x == 0) d_work = 0u;
    int g = blockIdx.x * 256 + threadIdx.x;
    if (g >= G_TOT) return;
    int ni = g / N_GRIDP;
    float gx = u[g * 3 + 0] * wlh[ni * 3 + 0];
    float gy = u[g * 3 + 1] * wlh[ni * 3 + 1];
    float gz = u[g * 3 + 2] * wlh[ni * 3 + 2];
    float yv = yaw[ni];
    float c = cosf(yv), s = sinf(yv);
    float rx = c * gx - s * gy;
    float ry = s * gx + c * gy;
    d_grid[g * 3 + 0] = rx + center[ni * 3 + 0];
    d_grid[g * 3 + 1] = ry + center[ni * 3 + 1];
    d_grid[g * 3 + 2] = gz + center[ni * 3 + 2];
}

// ---------------- k2: per-keypoint A = kp.w1[:3] + kf.w1[3:] ----------------
__global__ void __launch_bounds__(256) k_A(const float* __restrict__ kp, const float* __restrict__ kf,
                                           const float* __restrict__ w1_0, const float* __restrict__ w1_1)
{
    __shared__ float w1s[64 * 131];
    const float* w1 = blockIdx.y ? w1_1 : w1_0;
    int tid = threadIdx.y * 32 + threadIdx.x;
    for (int i = tid; i < 64 * 131; i += 256) w1s[i] = w1[i];
    __syncthreads();

    int l = threadIdx.x;
    int kbase = blockIdx.x * 64;
#pragma unroll 1
    for (int t = 0; t < 8; t++) {
        int k = kbase + t * 8 + threadIdx.y;
        float kx = kp[k * 3 + 0], ky = kp[k * 3 + 1], kz = kp[k * 3 + 2];
        float a0 = w1s[l * 131 + 0] * kx + w1s[l * 131 + 1] * ky + w1s[l * 131 + 2] * kz;
        float a1 = w1s[(l + 32) * 131 + 0] * kx + w1s[(l + 32) * 131 + 1] * ky + w1s[(l + 32) * 131 + 2] * kz;
#pragma unroll 4
        for (int c = 0; c < C_FEAT; c++) {
            float f = kf[c * N_KEY + k];
            a0 = fmaf(f, w1s[l * 131 + 3 + c], a0);
            a1 = fmaf(f, w1s[(l + 32) * 131 + 3 + c], a1);
        }
        d_A[blockIdx.y][k * 32 + l] = make_float2(a0, a1);
    }
}

// ---------------- k3: ball query + hit counts ----------------
__global__ void __launch_bounds__(256) k_ball(const float* __restrict__ kp)
{
    extern __shared__ float4 kpt[];   // 64KB dynamic
    for (int i = threadIdx.x; i < N_KEY; i += 256) {
        float kx = kp[i * 3 + 0], ky = kp[i * 3 + 1], kz = kp[i * 3 + 2];
        kpt[i] = make_float4(kx, ky, kz, kx * kx + ky * ky + kz * kz);
    }
    __syncthreads();

    int g = blockIdx.x * 256 + threadIdx.x;
    float gx = d_grid[g * 3 + 0], gy = d_grid[g * 3 + 1], gz = d_grid[g * 3 + 2];
    float gs = gx * gx + gy * gy + gz * gz;
    float m2x = -2.f * gx, m2y = -2.f * gy, m2z = -2.f * gz;

    int c0 = 0, c1 = 0, f0 = 0, f1 = 0;
    int* o0 = &d_idx[0][g * NS];
    int* o1 = &d_idx[1][g * NS];

#pragma unroll 4
    for (int k = 0; k < N_KEY; k++) {
        float4 v = kpt[k];
        float d2 = fmaf(m2x, v.x, fmaf(m2y, v.y, fmaf(m2z, v.z, gs + v.w)));
        if (d2 < 2.56f) {
            if (c1 < NS) { if (c1 == 0) f1 = k; o1[c1++] = k; }
            if (d2 < 0.64f) {
                if (c0 == 0) f0 = k;
                o0[c0++] = k;
                if (c0 == NS) break;   // r0 hits subset of r1 hits -> c1 full too
            }
        }
    }
    for (int n = c1; n < NS; n++) o1[n] = f1;
    for (int n = c0; n < NS; n++) o0[n] = f0;
    // duplicates beyond count don't change the max -> only compute cnt samples
    d_cnt[0][g] = (c0 > 0) ? c0 : 1;
    d_cnt[1][g] = (c1 > 0) ? c1 : 1;
}

// ---------------- k4: branch MLP + maxpool, persistent work-stealing ----------
__global__ void __launch_bounds__(256, 1) k_branch(
    const float* __restrict__ w1_0, const float* __restrict__ g1_0, const float* __restrict__ b1_0,
    const float* __restrict__ w2_0, const float* __restrict__ g2_0, const float* __restrict__ b2_0,
    const float* __restrict__ w1_1, const float* __restrict__ g1_1, const float* __restrict__ b1_1,
    const float* __restrict__ w2_1, const float* __restrict__ g2_1, const float* __restrict__ b2_1)
{
    const int lane = threadIdx.x & 31;
    const int warp = threadIdx.x >> 5;
    const int tid  = threadIdx.x;

    __shared__ __align__(16) float hbuf[8][2][64];
    __shared__ int s_chunk;

    // per-branch state (reloaded when branch changes; <=2x per block)
    int cur_b = -1;
    ull w2lo[32], w2hi[32];
    float g1lo = 0, g1hi = 0, b1lo = 0, b1hi = 0, g2lo = 0, g2hi = 0, b2lo = 0, b2hi = 0;
    float w1x0 = 0, w1y0 = 0, w1z0 = 0, w1x1 = 0, w1y1 = 0, w1z1 = 0;
    const float2* A2 = d_A[0];
    const int*    idxp = d_idx[0];
    const int*    cntp = d_cnt[0];

    for (;;) {
        __syncthreads();
        if (tid == 0) s_chunk = (int)atomicAdd(&d_work, 1u);
        __syncthreads();
        int chunk = s_chunk;
        if (chunk >= NCHUNK) break;

        int b = (chunk >= NCHUNK / 2);
        int gbase = (chunk - b * (NCHUNK / 2)) * 8;

        if (b != cur_b) {
            cur_b = b;
            const float* w1 = b ? w1_1 : w1_0;
            const float* g1 = b ? g1_1 : g1_0;
            const float* b1 = b ? b1_1 : b1_0;
            const float* w2 = b ? w2_1 : w2_0;
            const float* g2 = b ? g2_1 : g2_0;
            const float* b2 = b ? b2_1 : b2_0;
            const double2* w2d = (const double2*)w2;
#pragma unroll
            for (int jj = 0; jj < 16; jj++) {
                double2 vlo = w2d[lane * 16 + jj];
                double2 vhi = w2d[(lane + 32) * 16 + jj];
                w2lo[2 * jj] = d2u(vlo.x); w2lo[2 * jj + 1] = d2u(vlo.y);
                w2hi[2 * jj] = d2u(vhi.x); w2hi[2 * jj + 1] = d2u(vhi.y);
            }
            g1lo = g1[lane]; g1hi = g1[lane + 32];
            b1lo = b1[lane]; b1hi = b1[lane + 32];
            g2lo = g2[lane]; g2hi = g2[lane + 32];
            b2lo = b2[lane]; b2hi = b2[lane + 32];
            w1x0 = w1[lane * 131 + 0]; w1y0 = w1[lane * 131 + 1]; w1z0 = w1[lane * 131 + 2];
            w1x1 = w1[(lane + 32) * 131 + 0]; w1y1 = w1[(lane + 32) * 131 + 1]; w1z1 = w1[(lane + 32) * 131 + 2];
            A2 = d_A[b];
            idxp = d_idx[b];
            cntp = d_cnt[b];
        }

        int g = gbase + warp;
        float gx = d_grid[g * 3 + 0], gy = d_grid[g * 3 + 1], gz = d_grid[g * 3 + 2];
        float qlo = w1x0 * gx + w1y0 * gy + w1z0 * gz;
        float qhi = w1x1 * gx + w1y1 * gy + w1z1 * gz;
        int cnt = cntp[g];
        int kreg = idxp[g * NS + (lane & 15)];
        float mxA = -1e30f, mxB = -1e30f;

        int kcur = __shfl_sync(0xffffffffu, kreg, 0);
        float2 av = A2[kcur * 32 + lane];

#pragma unroll 1
        for (int n = 0; n < cnt; n++) {
            int nn = (n + 1 < cnt) ? (n + 1) : n;
            int knext = __shfl_sync(0xffffffffu, kreg, nn);
            float2 avn = A2[knext * 32 + lane];

            float* hb = hbuf[warp][n & 1];
            hb[lane]      = fmaxf(fmaf(g1lo, av.x - qlo, b1lo), 0.f);
            hb[lane + 32] = fmaxf(fmaf(g1hi, av.y - qhi, b1hi), 0.f);
            __syncwarp();

            ull a0 = 0, a1 = 0, c0 = 0, c1 = 0;
            const double2* h2 = (const double2*)hb;
#pragma unroll
            for (int jj = 0; jj < 8; jj++) {
                double2 v0 = h2[2 * jj];
                double2 v1 = h2[2 * jj + 1];
                fma2(a0, d2u(v0.x), w2lo[4 * jj + 0]);
                fma2(a1, d2u(v0.y), w2lo[4 * jj + 1]);
                fma2(c0, d2u(v0.x), w2hi[4 * jj + 0]);
                fma2(c1, d2u(v0.y), w2hi[4 * jj + 1]);
                fma2(a0, d2u(v1.x), w2lo[4 * jj + 2]);
                fma2(a1, d2u(v1.y), w2lo[4 * jj + 3]);
                fma2(c0, d2u(v1.x), w2hi[4 * jj + 2]);
                fma2(c1, d2u(v1.y), w2hi[4 * jj + 3]);
            }
            float2 pa0 = unpack2(a0), pa1 = unpack2(a1);
            float2 pc0 = unpack2(c0), pc1 = unpack2(c1);
            float dotA = (pa0.x + pa0.y) + (pa1.x + pa1.y);
            float dotB = (pc0.x + pc0.y) + (pc1.x + pc1.y);
            mxA = fmaxf(mxA, fmaf(g2lo, dotA, b2lo));
            mxB = fmaxf(mxB, fmaf(g2hi, dotB, b2hi));
            av = avn;
        }
        int ni = g / N_GRIDP, mi = g % N_GRIDP;
        int cpA = b * 64 + lane;
        d_perm[mi * 16384 + cpA * 128 + ni] = fmaxf(mxA, 0.f);
        d_perm[mi * 16384 + (cpA + 32) * 128 + ni] = fmaxf(mxB, 0.f);
    }
}

// ---------------- k5: reduction GEMM layer1, split-K=36, f32x2 ----------------
__global__ void __launch_bounds__(256) k_red1(const float* __restrict__ W)
{
    __shared__ __align__(16) float As[32][132];
    __shared__ __align__(16) float Bs[32][68];
    const int ob = blockIdx.x * 64;
    const int kbase = blockIdx.y * KCHUNK;
    const int tid = threadIdx.x;
    const int tx = tid & 15, ty = tid >> 4;

    ull acc[4][4];
#pragma unroll
    for (int r = 0; r < 4; r++)
#pragma unroll
        for (int c = 0; c < 4; c++) acc[r][c] = 0;

    for (int kc = 0; kc < KCHUNK; kc += 32) {
        int k0 = kbase + kc;
#pragma unroll
        for (int r = 0; r < 16; r++) {
            int e = tid + 256 * r;
            int i = e >> 5, kk = e & 31;
            As[kk][i] = d_perm[i * K_RED + k0 + kk];
        }
#pragma unroll
        for (int r = 0; r < 8; r++) {
            int e = tid + 256 * r;
            int o = e >> 5, kk = e & 31;
            Bs[kk][o] = W[(ob + o) * K_RED + k0 + kk];
        }
        __syncthreads();
#pragma unroll
        for (int kk = 0; kk < 32; kk++) {
            double2 a01 = *(const double2*)&As[kk][ty * 8];
            double2 a23 = *(const double2*)&As[kk][ty * 8 + 4];
            float4 bv = *(const float4*)&Bs[kk][tx * 4];
            ull ap0 = d2u(a01.x), ap1 = d2u(a01.y), ap2 = d2u(a23.x), ap3 = d2u(a23.y);
            ull b0 = splat2(bv.x), b1 = splat2(bv.y), b2 = splat2(bv.z), b3 = splat2(bv.w);
            fma2(acc[0][0], ap0, b0); fma2(acc[0][1], ap0, b1); fma2(acc[0][2], ap0, b2); fma2(acc[0][3], ap0, b3);
            fma2(acc[1][0], ap1, b0); fma2(acc[1][1], ap1, b1); fma2(acc[1][2], ap1, b2); fma2(acc[1][3], ap1, b3);
            fma2(acc[2][0], ap2, b0); fma2(acc[2][1], ap2, b1); fma2(acc[2][2], ap2, b2); fma2(acc[2][3], ap2, b3);
            fma2(acc[3][0], ap3, b0); fma2(acc[3][1], ap3, b1); fma2(acc[3][2], ap3, b2); fma2(acc[3][3], ap3, b3);
        }
        __syncthreads();
    }
    float* outp = d_partial[blockIdx.y];
#pragma unroll
    for (int rp = 0; rp < 4; rp++)
#pragma unroll
        for (int c = 0; c < 4; c++) {
            float2 v = unpack2(acc[rp][c]);
            outp[(ty * 8 + 2 * rp) * 256 + ob + tx * 4 + c] = v.x;
            outp[(ty * 8 + 2 * rp + 1) * 256 + ob + tx * 4 + c] = v.y;
        }
}

// ---------------- k6: partial reduce + bias + relu ----------------
__global__ void k_redfin(const float* __restrict__ b1)
{
    int t = blockIdx.x * 256 + threadIdx.x;
    float s = b1[t & 255];
#pragma unroll
    for (int ks = 0; ks < KSPLIT; ks++) s += d_partial[ks][t];
    d_hbuf[t] = fmaxf(s, 0.f);
}

// ---------------- k6b: transpose W2 ----------------
__global__ void k_w2t(const float* __restrict__ W2)
{
    __shared__ float tbuf[32][33];
    int x = blockIdx.x * 32 + threadIdx.x;
    int y0 = blockIdx.y * 32;
#pragma unroll
    for (int r = threadIdx.y; r < 32; r += 8)
        tbuf[r][threadIdx.x] = W2[(y0 + r) * 256 + x];
    __syncthreads();
    int xo = blockIdx.y * 32 + threadIdx.x;
#pragma unroll
    for (int r = threadIdx.y; r < 32; r += 8)
        d_w2t[(blockIdx.x * 32 + r) * 256 + xo] = tbuf[threadIdx.x][r];
}

// ---------------- k7: layer2 256x256 + relu ----------------
__global__ void __launch_bounds__(256) k_red2(const float* __restrict__ b2, float* __restrict__ out)
{
    __shared__ float hs[256];
    int i = blockIdx.x;
    hs[threadIdx.x] = d_hbuf[i * 256 + threadIdx.x];
    __syncthreads();
    int o = threadIdx.x;
    float s = b2[o];
#pragma unroll 8
    for (int c = 0; c < 256; c++) s = fmaf(hs[c], d_w2t[c * 256 + o], s);
    out[i * 256 + o] = fmaxf(s, 0.f);
}

// ---------------- launch ----------------
extern "C" void kernel_launch(void* const* d_in, const int* in_sizes, int n_in,
                              void* d_out, int out_size)
{
    const float* wlh    = (const float*)d_in[0];
    const float* center = (const float*)d_in[1];
    const float* yaw    = (const float*)d_in[2];
    const float* u      = (const float*)d_in[3];
    const float* kp     = (const float*)d_in[4];
    const float* kf     = (const float*)d_in[5];
    const float* pn0_w1 = (const float*)d_in[6];
    const float* pn0_g1 = (const float*)d_in[7];
    const float* pn0_b1 = (const float*)d_in[8];
    const float* pn0_w2 = (const float*)d_in[9];
    const float* pn0_g2 = (const float*)d_in[10];
    const float* pn0_b2 = (const float*)d_in[11];
    const float* pn1_w1 = (const float*)d_in[12];
    const float* pn1_g1 = (const float*)d_in[13];
    const float* pn1_b1 = (const float*)d_in[14];
    const float* pn1_w2 = (const float*)d_in[15];
    const float* pn1_g2 = (const float*)d_in[16];
    const float* pn1_b2 = (const float*)d_in[17];
    const float* red_w1 = (const float*)d_in[18];
    const float* red_b1 = (const float*)d_in[19];
    const float* red_w2 = (const float*)d_in[20];
    const float* red_b2 = (const float*)d_in[21];
    float* out = (float*)d_out;

    cudaFuncSetAttribute(k_ball, cudaFuncAttributeMaxDynamicSharedMemorySize, 65536);

    k_grid<<<(G_TOT + 255) / 256, 256>>>(wlh, center, yaw, u);
    k_ball<<<G_TOT / 256, 256, 65536>>>(kp);
    k_A<<<dim3(64, 2), dim3(32, 8)>>>(kp, kf, pn0_w1, pn1_w1);
    k_branch<<<148, 256>>>(pn0_w1, pn0_g1, pn0_b1, pn0_w2, pn0_g2, pn0_b2,
                           pn1_w1, pn1_g1, pn1_b1, pn1_w2, pn1_g2, pn1_b2);
    k_w2t<<<dim3(8, 8), dim3(32, 8)>>>(red_w2);
    k_red1<<<dim3(4, KSPLIT), 256>>>(red_w1);
    k_redfin<<<128, 256>>>(red_b1);
    k_red2<<<128, 256>>>(red_b2, out);
}

// round 7
// speedup vs baseline: 2.4491x; 1.1331x over previous
#include <cuda_runtime.h>
#include <cuda_bf16.h>

#define N_PROP 128
#define N_GRIDP 216
#define G_TOT  27648
#define N_KEY  4096
#define C_FEAT 128
#define NS     16
#define K_RED  27648
#define KSPLIT 36
#define KCHUNK 768
#define NCHUNK 3456              // 2 * 27648 / 16

typedef unsigned long long ull;

// ---------------- scratch ----------------
static __device__ float  d_grid[G_TOT * 3];
static __device__ float2 d_A[2][N_KEY * 32];
static __device__ int    d_idx[2][G_TOT * NS];
static __device__ int    d_cnt[2][G_TOT];
static __device__ float  d_perm[N_PROP * K_RED];
static __device__ float  d_partial[KSPLIT][N_PROP * 256];
static __device__ float  d_hbuf[N_PROP * 256];
static __device__ float  d_w2t[256 * 256];
static __device__ unsigned d_work;

// ---------------- f32x2 helpers ----------------
__device__ __forceinline__ ull splat2(float x) {
    ull r;
    asm("mov.b64 %0, {%1, %1};" : "=l"(r) : "f"(x));
    return r;
}
__device__ __forceinline__ void fma2(ull& acc, ull a, ull b) {
    asm("fma.rn.f32x2 %0, %1, %2, %0;" : "+l"(acc) : "l"(a), "l"(b));
}
__device__ __forceinline__ float2 unpack2(ull v) {
    float lo, hi;
    asm("mov.b64 {%0, %1}, %2;" : "=f"(lo), "=f"(hi) : "l"(v));
    return make_float2(lo, hi);
}
__device__ __forceinline__ ull d2u(double d) { return __double_as_longlong(d); }

// ---------------- k1: grid points (+ work counter reset) ----------------
__global__ void k_grid(const float* __restrict__ wlh, const float* __restrict__ center,
                       const float* __restrict__ yaw, const float* __restrict__ u)
{
    if (blockIdx.x == 0 && threadIdx.x == 0) d_work = 0u;
    int g = blockIdx.x * 256 + threadIdx.x;
    if (g >= G_TOT) return;
    int ni = g / N_GRIDP;
    float gx = u[g * 3 + 0] * wlh[ni * 3 + 0];
    float gy = u[g * 3 + 1] * wlh[ni * 3 + 1];
    float gz = u[g * 3 + 2] * wlh[ni * 3 + 2];
    float yv = yaw[ni];
    float c = cosf(yv), s = sinf(yv);
    float rx = c * gx - s * gy;
    float ry = s * gx + c * gy;
    d_grid[g * 3 + 0] = rx + center[ni * 3 + 0];
    d_grid[g * 3 + 1] = ry + center[ni * 3 + 1];
    d_grid[g * 3 + 2] = gz + center[ni * 3 + 2];
}

// ---------------- k2: per-keypoint A, kf staged coalesced in smem ----------------
// grid (64, 2): 64 keypoints per block, 256 threads (32 lanes x 8 warps)
__global__ void __launch_bounds__(256) k_A(const float* __restrict__ kp, const float* __restrict__ kf,
                                           const float* __restrict__ w1_0, const float* __restrict__ w1_1)
{
    __shared__ float w1s[64 * 131];           // 33.5 KB static
    extern __shared__ float kfs[];            // 128 c x 64 k = 32 KB dynamic
    const float* w1 = blockIdx.y ? w1_1 : w1_0;
    int tid = threadIdx.y * 32 + threadIdx.x;
    for (int i = tid; i < 64 * 131; i += 256) w1s[i] = w1[i];

    int kbase = blockIdx.x * 64;
    // coalesced kf tile load: row c holds 64 consecutive k's
    for (int e = tid; e < C_FEAT * 64; e += 256) {
        int c = e >> 6, kk = e & 63;
        kfs[c * 64 + kk] = kf[c * N_KEY + kbase + kk];
    }
    __syncthreads();

    int l = threadIdx.x;
#pragma unroll 1
    for (int t = 0; t < 8; t++) {
        int kk = t * 8 + threadIdx.y;          // local keypoint 0..63
        int k = kbase + kk;
        float kx = kp[k * 3 + 0], ky = kp[k * 3 + 1], kz = kp[k * 3 + 2];
        float a0 = w1s[l * 131 + 0] * kx + w1s[l * 131 + 1] * ky + w1s[l * 131 + 2] * kz;
        float a1 = w1s[(l + 32) * 131 + 0] * kx + w1s[(l + 32) * 131 + 1] * ky + w1s[(l + 32) * 131 + 2] * kz;
#pragma unroll 4
        for (int c = 0; c < C_FEAT; c++) {
            float f = kfs[c * 64 + kk];
            a0 = fmaf(f, w1s[l * 131 + 3 + c], a0);
            a1 = fmaf(f, w1s[(l + 32) * 131 + 3 + c], a1);
        }
        d_A[blockIdx.y][k * 32 + l] = make_float2(a0, a1);
    }
}

// ---------------- k3: ball query + hit counts ----------------
__global__ void __launch_bounds__(256) k_ball(const float* __restrict__ kp)
{
    extern __shared__ float4 kpt[];   // 64KB dynamic
    for (int i = threadIdx.x; i < N_KEY; i += 256) {
        float kx = kp[i * 3 + 0], ky = kp[i * 3 + 1], kz = kp[i * 3 + 2];
        kpt[i] = make_float4(kx, ky, kz, kx * kx + ky * ky + kz * kz);
    }
    __syncthreads();

    int g = blockIdx.x * 256 + threadIdx.x;
    float gx = d_grid[g * 3 + 0], gy = d_grid[g * 3 + 1], gz = d_grid[g * 3 + 2];
    float gs = gx * gx + gy * gy + gz * gz;
    float m2x = -2.f * gx, m2y = -2.f * gy, m2z = -2.f * gz;

    int c0 = 0, c1 = 0, f0 = 0, f1 = 0;
    int* o0 = &d_idx[0][g * NS];
    int* o1 = &d_idx[1][g * NS];

#pragma unroll 4
    for (int k = 0; k < N_KEY; k++) {
        float4 v = kpt[k];
        float d2 = fmaf(m2x, v.x, fmaf(m2y, v.y, fmaf(m2z, v.z, gs + v.w)));
        if (d2 < 2.56f) {
            if (c1 < NS) { if (c1 == 0) f1 = k; o1[c1++] = k; }
            if (d2 < 0.64f) {
                if (c0 == 0) f0 = k;
                o0[c0++] = k;
                if (c0 == NS) break;   // r0 hits subset of r1 hits -> c1 full too
            }
        }
    }
    for (int n = c1; n < NS; n++) o1[n] = f1;
    for (int n = c0; n < NS; n++) o0[n] = f0;
    d_cnt[0][g] = (c0 > 0) ? c0 : 1;
    d_cnt[1][g] = (c1 > 0) ? c1 : 1;
}

// ---------------- k4: branch MLP + maxpool, 2 samples/iter, work-stealing -----
__global__ void __launch_bounds__(256, 1) k_branch(
    const float* __restrict__ w1_0, const float* __restrict__ g1_0, const float* __restrict__ b1_0,
    const float* __restrict__ w2_0, const float* __restrict__ g2_0, const float* __restrict__ b2_0,
    const float* __restrict__ w1_1, const float* __restrict__ g1_1, const float* __restrict__ b1_1,
    const float* __restrict__ w2_1, const float* __restrict__ g2_1, const float* __restrict__ b2_1)
{
    const int lane = threadIdx.x & 31;
    const int warp = threadIdx.x >> 5;
    const int tid  = threadIdx.x;

    __shared__ __align__(16) float hbuf[8][2][64];   // per warp: 2 sample buffers
    __shared__ int s_chunk;

    int cur_b = -1;
    ull w2lo[32], w2hi[32];
    float g1lo = 0, g1hi = 0, b1lo = 0, b1hi = 0, g2lo = 0, g2hi = 0, b2lo = 0, b2hi = 0;
    float w1x0 = 0, w1y0 = 0, w1z0 = 0, w1x1 = 0, w1y1 = 0, w1z1 = 0;
    const float2* A2 = d_A[0];
    const int*    idxp = d_idx[0];
    const int*    cntp = d_cnt[0];

    for (;;) {
        __syncthreads();
        if (tid == 0) s_chunk = (int)atomicAdd(&d_work, 1u);
        __syncthreads();
        int chunk = s_chunk;
        if (chunk >= NCHUNK) break;

        int b = (chunk >= NCHUNK / 2);
        int gbase = (chunk - b * (NCHUNK / 2)) * 16;

        if (b != cur_b) {
            cur_b = b;
            const float* w1 = b ? w1_1 : w1_0;
            const float* g1 = b ? g1_1 : g1_0;
            const float* b1 = b ? b1_1 : b1_0;
            const float* w2 = b ? w2_1 : w2_0;
            const float* g2 = b ? g2_1 : g2_0;
            const float* b2 = b ? b2_1 : b2_0;
            const double2* w2d = (const double2*)w2;
#pragma unroll
            for (int jj = 0; jj < 16; jj++) {
                double2 vlo = w2d[lane * 16 + jj];
                double2 vhi = w2d[(lane + 32) * 16 + jj];
                w2lo[2 * jj] = d2u(vlo.x); w2lo[2 * jj + 1] = d2u(vlo.y);
                w2hi[2 * jj] = d2u(vhi.x); w2hi[2 * jj + 1] = d2u(vhi.y);
            }
            g1lo = g1[lane]; g1hi = g1[lane + 32];
            b1lo = b1[lane]; b1hi = b1[lane + 32];
            g2lo = g2[lane]; g2hi = g2[lane + 32];
            b2lo = b2[lane]; b2hi = b2[lane + 32];
            w1x0 = w1[lane * 131 + 0]; w1y0 = w1[lane * 131 + 1]; w1z0 = w1[lane * 131 + 2];
            w1x1 = w1[(lane + 32) * 131 + 0]; w1y1 = w1[(lane + 32) * 131 + 1]; w1z1 = w1[(lane + 32) * 131 + 2];
            A2 = d_A[b];
            idxp = d_idx[b];
            cntp = d_cnt[b];
        }

#pragma unroll 1
        for (int gi = 0; gi < 2; gi++) {
            int g = gbase + warp * 2 + gi;
            float gx = d_grid[g * 3 + 0], gy = d_grid[g * 3 + 1], gz = d_grid[g * 3 + 2];
            float qlo = w1x0 * gx + w1y0 * gy + w1z0 * gz;
            float qhi = w1x1 * gx + w1y1 * gy + w1z1 * gz;
            int cnt = cntp[g];
            int kreg = idxp[g * NS + (lane & 15)];
            float mxA = -1e30f, mxB = -1e30f;

            // prologue: samples 0 and min(1, cnt-1)   (duplicates idempotent for max)
            int i1 = (1 < cnt) ? 1 : (cnt - 1);
            int ka = __shfl_sync(0xffffffffu, kreg, 0);
            int kb = __shfl_sync(0xffffffffu, kreg, i1);
            float2 av0 = A2[ka * 32 + lane];
            float2 av1 = A2[kb * 32 + lane];

            float* hb0 = hbuf[warp][0];
            float* hb1 = hbuf[warp][1];

#pragma unroll 1
            for (int n = 0; n < cnt; n += 2) {
                int j0 = (n + 2 < cnt) ? n + 2 : cnt - 1;
                int j1 = (n + 3 < cnt) ? n + 3 : cnt - 1;
                int kn0 = __shfl_sync(0xffffffffu, kreg, j0);
                int kn1 = __shfl_sync(0xffffffffu, kreg, j1);
                float2 nx0 = A2[kn0 * 32 + lane];
                float2 nx1 = A2[kn1 * 32 + lane];

                hb0[lane]      = fmaxf(fmaf(g1lo, av0.x - qlo, b1lo), 0.f);
                hb0[lane + 32] = fmaxf(fmaf(g1hi, av0.y - qhi, b1hi), 0.f);
                hb1[lane]      = fmaxf(fmaf(g1lo, av1.x - qlo, b1lo), 0.f);
                hb1[lane + 32] = fmaxf(fmaf(g1hi, av1.y - qhi, b1hi), 0.f);
                __syncwarp();

                ull a0 = 0, a1 = 0, c0 = 0, c1 = 0;      // sample n
                ull e0 = 0, e1 = 0, f0 = 0, f1 = 0;      // sample n+1
                const double2* h0 = (const double2*)hb0;
                const double2* h1 = (const double2*)hb1;
#pragma unroll
                for (int jj = 0; jj < 8; jj++) {
                    ull wl0 = w2lo[4 * jj + 0], wl1 = w2lo[4 * jj + 1];
                    ull wl2 = w2lo[4 * jj + 2], wl3 = w2lo[4 * jj + 3];
                    ull wh0 = w2hi[4 * jj + 0], wh1 = w2hi[4 * jj + 1];
                    ull wh2 = w2hi[4 * jj + 2], wh3 = w2hi[4 * jj + 3];
                    double2 v0 = h0[2 * jj], v1 = h0[2 * jj + 1];
                    double2 u0 = h1[2 * jj], u1 = h1[2 * jj + 1];
                    fma2(a0, d2u(v0.x), wl0); fma2(e0, d2u(u0.x), wl0);
                    fma2(a1, d2u(v0.y), wl1); fma2(e1, d2u(u0.y), wl1);
                    fma2(c0, d2u(v0.x), wh0); fma2(f0, d2u(u0.x), wh0);
                    fma2(c1, d2u(v0.y), wh1); fma2(f1, d2u(u0.y), wh1);
                    fma2(a0, d2u(v1.x), wl2); fma2(e0, d2u(u1.x), wl2);
                    fma2(a1, d2u(v1.y), wl3); fma2(e1, d2u(u1.y), wl3);
                    fma2(c0, d2u(v1.x), wh2); fma2(f0, d2u(u1.x), wh2);
                    fma2(c1, d2u(v1.y), wh3); fma2(f1, d2u(u1.y), wh3);
                }
                __syncwarp();

                float2 p, q2;
                p = unpack2(a0); q2 = unpack2(a1);
                mxA = fmaxf(mxA, fmaf(g2lo, (p.x + p.y) + (q2.x + q2.y), b2lo));
                p = unpack2(c0); q2 = unpack2(c1);
                mxB = fmaxf(mxB, fmaf(g2hi, (p.x + p.y) + (q2.x + q2.y), b2hi));
                p = unpack2(e0); q2 = unpack2(e1);
                mxA = fmaxf(mxA, fmaf(g2lo, (p.x + p.y) + (q2.x + q2.y), b2lo));
                p = unpack2(f0); q2 = unpack2(f1);
                mxB = fmaxf(mxB, fmaf(g2hi, (p.x + p.y) + (q2.x + q2.y), b2hi));

                av0 = nx0;
                av1 = nx1;
            }
            int ni = g / N_GRIDP, mi = g % N_GRIDP;
            int cpA = b * 64 + lane;
            d_perm[mi * 16384 + cpA * 128 + ni] = fmaxf(mxA, 0.f);
            d_perm[mi * 16384 + (cpA + 32) * 128 + ni] = fmaxf(mxB, 0.f);
        }
    }
}

// ---------------- k5: reduction GEMM layer1, split-K=36, f32x2 ----------------
__global__ void __launch_bounds__(256) k_red1(const float* __restrict__ W)
{
    __shared__ __align__(16) float As[32][132];
    __shared__ __align__(16) float Bs[32][68];
    const int ob = blockIdx.x * 64;
    const int kbase = blockIdx.y * KCHUNK;
    const int tid = threadIdx.x;
    const int tx = tid & 15, ty = tid >> 4;

    ull acc[4][4];
#pragma unroll
    for (int r = 0; r < 4; r++)
#pragma unroll
        for (int c = 0; c < 4; c++) acc[r][c] = 0;

    for (int kc = 0; kc < KCHUNK; kc += 32) {
        int k0 = kbase + kc;
#pragma unroll
        for (int r = 0; r < 16; r++) {
            int e = tid + 256 * r;
            int i = e >> 5, kk = e & 31;
            As[kk][i] = d_perm[i * K_RED + k0 + kk];
        }
#pragma unroll
        for (int r = 0; r < 8; r++) {
            int e = tid + 256 * r;
            int o = e >> 5, kk = e & 31;
            Bs[kk][o] = W[(ob + o) * K_RED + k0 + kk];
        }
        __syncthreads();
#pragma unroll
        for (int kk = 0; kk < 32; kk++) {
            double2 a01 = *(const double2*)&As[kk][ty * 8];
            double2 a23 = *(const double2*)&As[kk][ty * 8 + 4];
            float4 bv = *(const float4*)&Bs[kk][tx * 4];
            ull ap0 = d2u(a01.x), ap1 = d2u(a01.y), ap2 = d2u(a23.x), ap3 = d2u(a23.y);
            ull b0 = splat2(bv.x), b1 = splat2(bv.y), b2 = splat2(bv.z), b3 = splat2(bv.w);
            fma2(acc[0][0], ap0, b0); fma2(acc[0][1], ap0, b1); fma2(acc[0][2], ap0, b2); fma2(acc[0][3], ap0, b3);
            fma2(acc[1][0], ap1, b0); fma2(acc[1][1], ap1, b1); fma2(acc[1][2], ap1, b2); fma2(acc[1][3], ap1, b3);
            fma2(acc[2][0], ap2, b0); fma2(acc[2][1], ap2, b1); fma2(acc[2][2], ap2, b2); fma2(acc[2][3], ap2, b3);
            fma2(acc[3][0], ap3, b0); fma2(acc[3][1], ap3, b1); fma2(acc[3][2], ap3, b2); fma2(acc[3][3], ap3, b3);
        }
        __syncthreads();
    }
    float* outp = d_partial[blockIdx.y];
#pragma unroll
    for (int rp = 0; rp < 4; rp++)
#pragma unroll
        for (int c = 0; c < 4; c++) {
            float2 v = unpack2(acc[rp][c]);
            outp[(ty * 8 + 2 * rp) * 256 + ob + tx * 4 + c] = v.x;
            outp[(ty * 8 + 2 * rp + 1) * 256 + ob + tx * 4 + c] = v.y;
        }
}

// ---------------- k6: partial reduce + bias + relu ----------------
__global__ void k_redfin(const float* __restrict__ b1)
{
    int t = blockIdx.x * 256 + threadIdx.x;
    float s = b1[t & 255];
#pragma unroll
    for (int ks = 0; ks < KSPLIT; ks++) s += d_partial[ks][t];
    d_hbuf[t] = fmaxf(s, 0.f);
}

// ---------------- k6b: transpose W2 ----------------
__global__ void k_w2t(const float* __restrict__ W2)
{
    __shared__ float tbuf[32][33];
    int x = blockIdx.x * 32 + threadIdx.x;
    int y0 = blockIdx.y * 32;
#pragma unroll
    for (int r = threadIdx.y; r < 32; r += 8)
        tbuf[r][threadIdx.x] = W2[(y0 + r) * 256 + x];
    __syncthreads();
    int xo = blockIdx.y * 32 + threadIdx.x;
#pragma unroll
    for (int r = threadIdx.y; r < 32; r += 8)
        d_w2t[(blockIdx.x * 32 + r) * 256 + xo] = tbuf[threadIdx.x][r];
}

// ---------------- k7: layer2 256x256 + relu ----------------
__global__ void __launch_bounds__(256) k_red2(const float* __restrict__ b2, float* __restrict__ out)
{
    __shared__ float hs[256];
    int i = blockIdx.x;
    hs[threadIdx.x] = d_hbuf[i * 256 + threadIdx.x];
    __syncthreads();
    int o = threadIdx.x;
    float s = b2[o];
#pragma unroll 8
    for (int c = 0; c < 256; c++) s = fmaf(hs[c], d_w2t[c * 256 + o], s);
    out[i * 256 + o] = fmaxf(s, 0.f);
}

// ---------------- launch ----------------
extern "C" void kernel_launch(void* const* d_in, const int* in_sizes, int n_in,
                              void* d_out, int out_size)
{
    const float* wlh    = (const float*)d_in[0];
    const float* center = (const float*)d_in[1];
    const float* yaw    = (const float*)d_in[2];
    const float* u      = (const float*)d_in[3];
    const float* kp     = (const float*)d_in[4];
    const float* kf     = (const float*)d_in[5];
    const float* pn0_w1 = (const float*)d_in[6];
    const float* pn0_g1 = (const float*)d_in[7];
    const float* pn0_b1 = (const float*)d_in[8];
    const float* pn0_w2 = (const float*)d_in[9];
    const float* pn0_g2 = (const float*)d_in[10];
    const float* pn0_b2 = (const float*)d_in[11];
    const float* pn1_w1 = (const float*)d_in[12];
    const float* pn1_g1 = (const float*)d_in[13];
    const float* pn1_b1 = (const float*)d_in[14];
    const float* pn1_w2 = (const float*)d_in[15];
    const float* pn1_g2 = (const float*)d_in[16];
    const float* pn1_b2 = (const float*)d_in[17];
    const float* red_w1 = (const float*)d_in[18];
    const float* red_b1 = (const float*)d_in[19];
    const float* red_w2 = (const float*)d_in[20];
    const float* red_b2 = (const float*)d_in[21];
    float* out = (float*)d_out;

    cudaFuncSetAttribute(k_ball, cudaFuncAttributeMaxDynamicSharedMemorySize, 65536);
    cudaFuncSetAttribute(k_A,    cudaFuncAttributeMaxDynamicSharedMemorySize, 32768);

    k_grid<<<(G_TOT + 255) / 256, 256>>>(wlh, center, yaw, u);
    k_ball<<<G_TOT / 256, 256, 65536>>>(kp);
    k_A<<<dim3(64, 2), dim3(32, 8), 32768>>>(kp, kf, pn0_w1, pn1_w1);
    k_branch<<<148, 256>>>(pn0_w1, pn0_g1, pn0_b1, pn0_w2, pn0_g2, pn0_b2,
                           pn1_w1, pn1_g1, pn1_b1, pn1_w2, pn1_g2, pn1_b2);
    k_w2t<<<dim3(8, 8), dim3(32, 8)>>>(red_w2);
    k_red1<<<dim3(4, KSPLIT), 256>>>(red_w1);
    k_redfin<<<128, 256>>>(red_b1);
    k_red2<<<128, 256>>>(red_b2, out);
}

// round 9
// speedup vs baseline: 3.0380x; 1.2405x over previous
#include <cuda_runtime.h>
#include <cuda_bf16.h>

#define N_PROP 128
#define N_GRIDP 216
#define G_TOT  27648
#define N_KEY  4096
#define C_FEAT 128
#define NS     16
#define K_RED  27648
#define KSPLIT 36
#define KCHUNK 768
#define NCHUNK 3456              // 2 * 27648 / 16

typedef unsigned long long ull;

// ---------------- scratch ----------------
static __device__ float  d_grid[G_TOT * 3];
static __device__ float2 d_A[2][N_KEY * 32];
static __device__ int    d_idx[2][G_TOT * NS];
static __device__ int    d_cnt[2][G_TOT];
static __device__ float  d_perm[N_PROP * K_RED];
static __device__ float  d_partial[KSPLIT][N_PROP * 256];
static __device__ float  d_hbuf[N_PROP * 256];
static __device__ float  d_w2t[256 * 256];
static __device__ unsigned d_work;

// ---------------- f32x2 helpers ----------------
__device__ __forceinline__ ull splat2(float x) {
    ull r;
    asm("mov.b64 %0, {%1, %1};" : "=l"(r) : "f"(x));
    return r;
}
__device__ __forceinline__ void fma2(ull& acc, ull a, ull b) {
    asm("fma.rn.f32x2 %0, %1, %2, %0;" : "+l"(acc) : "l"(a), "l"(b));
}
__device__ __forceinline__ float2 unpack2(ull v) {
    float lo, hi;
    asm("mov.b64 {%0, %1}, %2;" : "=f"(lo), "=f"(hi) : "l"(v));
    return make_float2(lo, hi);
}
__device__ __forceinline__ ull d2u(double d) { return __double_as_longlong(d); }

// ---------------- k1: grid points (+ work counter reset) ----------------
__global__ void k_grid(const float* __restrict__ wlh, const float* __restrict__ center,
                       const float* __restrict__ yaw, const float* __restrict__ u)
{
    if (blockIdx.x == 0 && threadIdx.x == 0) d_work = 0u;
    int g = blockIdx.x * 256 + threadIdx.x;
    if (g >= G_TOT) return;
    int ni = g / N_GRIDP;
    float gx = u[g * 3 + 0] * wlh[ni * 3 + 0];
    float gy = u[g * 3 + 1] * wlh[ni * 3 + 1];
    float gz = u[g * 3 + 2] * wlh[ni * 3 + 2];
    float yv = yaw[ni];
    float c = cosf(yv), s = sinf(yv);
    float rx = c * gx - s * gy;
    float ry = s * gx + c * gy;
    d_grid[g * 3 + 0] = rx + center[ni * 3 + 0];
    d_grid[g * 3 + 1] = ry + center[ni * 3 + 1];
    d_grid[g * 3 + 2] = gz + center[ni * 3 + 2];
}

// ---------------- k2: per-keypoint A, kf staged coalesced in smem ----------------
__global__ void __launch_bounds__(256) k_A(const float* __restrict__ kp, const float* __restrict__ kf,
                                           const float* __restrict__ w1_0, const float* __restrict__ w1_1)
{
    __shared__ float w1s[64 * 131];
    extern __shared__ float kfs[];            // 128 c x 64 k = 32 KB dynamic
    const float* w1 = blockIdx.y ? w1_1 : w1_0;
    int tid = threadIdx.y * 32 + threadIdx.x;
    for (int i = tid; i < 64 * 131; i += 256) w1s[i] = w1[i];

    int kbase = blockIdx.x * 64;
    for (int e = tid; e < C_FEAT * 64; e += 256) {
        int c = e >> 6, kk = e & 63;
        kfs[c * 64 + kk] = kf[c * N_KEY + kbase + kk];
    }
    __syncthreads();

    int l = threadIdx.x;
#pragma unroll 1
    for (int t = 0; t < 8; t++) {
        int kk = t * 8 + threadIdx.y;
        int k = kbase + kk;
        float kx = kp[k * 3 + 0], ky = kp[k * 3 + 1], kz = kp[k * 3 + 2];
        float a0 = w1s[l * 131 + 0] * kx + w1s[l * 131 + 1] * ky + w1s[l * 131 + 2] * kz;
        float a1 = w1s[(l + 32) * 131 + 0] * kx + w1s[(l + 32) * 131 + 1] * ky + w1s[(l + 32) * 131 + 2] * kz;
#pragma unroll 4
        for (int c = 0; c < C_FEAT; c++) {
            float f = kfs[c * 64 + kk];
            a0 = fmaf(f, w1s[l * 131 + 3 + c], a0);
            a1 = fmaf(f, w1s[(l + 32) * 131 + 3 + c], a1);
        }
        d_A[blockIdx.y][k * 32 + l] = make_float2(a0, a1);
    }
}

// ---------------- k3: ball query, 4-key min-filter fast path ----------------
#define BALL_CHECK(D2V, KK)                                          \
    if ((D2V) < 2.56f) {                                             \
        if (c1 < NS) { if (c1 == 0) f1 = (KK); o1[c1++] = (KK); }    \
        if ((D2V) < 0.64f) {                                         \
            if (c0 == 0) f0 = (KK);                                  \
            o0[c0++] = (KK);                                         \
            if (c0 == NS) { done = true; }                           \
        }                                                            \
    }

__global__ void __launch_bounds__(256) k_ball(const float* __restrict__ kp)
{
    extern __shared__ float4 kpt[];   // 64KB dynamic
    for (int i = threadIdx.x; i < N_KEY; i += 256) {
        float kx = kp[i * 3 + 0], ky = kp[i * 3 + 1], kz = kp[i * 3 + 2];
        kpt[i] = make_float4(kx, ky, kz, kx * kx + ky * ky + kz * kz);
    }
    __syncthreads();

    int g = blockIdx.x * 256 + threadIdx.x;
    float gx = d_grid[g * 3 + 0], gy = d_grid[g * 3 + 1], gz = d_grid[g * 3 + 2];
    float gs = gx * gx + gy * gy + gz * gz;
    float m2x = -2.f * gx, m2y = -2.f * gy, m2z = -2.f * gz;

    int c0 = 0, c1 = 0, f0 = 0, f1 = 0;
    bool done = false;
    int* o0 = &d_idx[0][g * NS];
    int* o1 = &d_idx[1][g * NS];

#pragma unroll 1
    for (int k = 0; k < N_KEY; k += 4) {
        float4 v0 = kpt[k + 0];
        float4 v1 = kpt[k + 1];
        float4 v2 = kpt[k + 2];
        float4 v3 = kpt[k + 3];
        float d20 = fmaf(m2x, v0.x, fmaf(m2y, v0.y, fmaf(m2z, v0.z, gs + v0.w)));
        float d21 = fmaf(m2x, v1.x, fmaf(m2y, v1.y, fmaf(m2z, v1.z, gs + v1.w)));
        float d22 = fmaf(m2x, v2.x, fmaf(m2y, v2.y, fmaf(m2z, v2.z, gs + v2.w)));
        float d23 = fmaf(m2x, v3.x, fmaf(m2y, v3.y, fmaf(m2z, v3.z, gs + v3.w)));
        if (fminf(fminf(d20, d21), fminf(d22, d23)) < 2.56f) {   // rare
            BALL_CHECK(d20, k + 0)
            if (!done) { BALL_CHECK(d21, k + 1) }
            if (!done) { BALL_CHECK(d22, k + 2) }
            if (!done) { BALL_CHECK(d23, k + 3) }
            if (done) break;
        }
    }
    for (int n = c1; n < NS; n++) o1[n] = f1;
    for (int n = c0; n < NS; n++) o0[n] = f0;
    d_cnt[0][g] = (c0 > 0) ? c0 : 1;
    d_cnt[1][g] = (c1 > 0) ? c1 : 1;
}

// ---------------- k4: branch MLP + maxpool, 4-deep prefetch pipeline ----------
__global__ void __launch_bounds__(256, 1) k_branch(
    const float* __restrict__ w1_0, const float* __restrict__ g1_0, const float* __restrict__ b1_0,
    const float* __restrict__ w2_0, const float* __restrict__ g2_0, const float* __restrict__ b2_0,
    const float* __restrict__ w1_1, const float* __restrict__ g1_1, const float* __restrict__ b1_1,
    const float* __restrict__ w2_1, const float* __restrict__ g2_1, const float* __restrict__ b2_1)
{
    const int lane = threadIdx.x & 31;
    const int warp = threadIdx.x >> 5;
    const int tid  = threadIdx.x;

    __shared__ __align__(16) float hbuf[8][2][64];
    __shared__ int s_chunk;

    int cur_b = -1;
    ull w2lo[32], w2hi[32];
    float g1lo = 0, g1hi = 0, b1lo = 0, b1hi = 0, g2lo = 0, g2hi = 0, b2lo = 0, b2hi = 0;
    float w1x0 = 0, w1y0 = 0, w1z0 = 0, w1x1 = 0, w1y1 = 0, w1z1 = 0;
    const float2* A2 = d_A[0];
    const int*    idxp = d_idx[0];
    const int*    cntp = d_cnt[0];

    for (;;) {
        __syncthreads();
        if (tid == 0) s_chunk = (int)atomicAdd(&d_work, 1u);
        __syncthreads();
        int chunk = s_chunk;
        if (chunk >= NCHUNK) break;

        int b = (chunk >= NCHUNK / 2);
        int gbase = (chunk - b * (NCHUNK / 2)) * 16;

        if (b != cur_b) {
            cur_b = b;
            const float* w1 = b ? w1_1 : w1_0;
            const float* g1 = b ? g1_1 : g1_0;
            const float* b1 = b ? b1_1 : b1_0;
            const float* w2 = b ? w2_1 : w2_0;
            const float* g2 = b ? g2_1 : g2_0;
            const float* b2 = b ? b2_1 : b2_0;
            const double2* w2d = (const double2*)w2;
#pragma unroll
            for (int jj = 0; jj < 16; jj++) {
                double2 vlo = w2d[lane * 16 + jj];
                double2 vhi = w2d[(lane + 32) * 16 + jj];
                w2lo[2 * jj] = d2u(vlo.x); w2lo[2 * jj + 1] = d2u(vlo.y);
                w2hi[2 * jj] = d2u(vhi.x); w2hi[2 * jj + 1] = d2u(vhi.y);
            }
            g1lo = g1[lane]; g1hi = g1[lane + 32];
            b1lo = b1[lane]; b1hi = b1[lane + 32];
            g2lo = g2[lane]; g2hi = g2[lane + 32];
            b2lo = b2[lane]; b2hi = b2[lane + 32];
            w1x0 = w1[lane * 131 + 0]; w1y0 = w1[lane * 131 + 1]; w1z0 = w1[lane * 131 + 2];
            w1x1 = w1[(lane + 32) * 131 + 0]; w1y1 = w1[(lane + 32) * 131 + 1]; w1z1 = w1[(lane + 32) * 131 + 2];
            A2 = d_A[b];
            idxp = d_idx[b];
            cntp = d_cnt[b];
        }

#pragma unroll 1
        for (int gi = 0; gi < 2; gi++) {
            int g = gbase + warp * 2 + gi;
            float gx = d_grid[g * 3 + 0], gy = d_grid[g * 3 + 1], gz = d_grid[g * 3 + 2];
            float qlo = w1x0 * gx + w1y0 * gy + w1z0 * gz;
            float qhi = w1x1 * gx + w1y1 * gy + w1z1 * gz;
            int cnt = cntp[g];
            int cm1 = cnt - 1;
            int kreg = idxp[g * NS + (lane & 15)];
            float mxA = -1e30f, mxB = -1e30f;

            // 4-deep pipeline: duplicates (clamped indices) are idempotent under max
            int i1 = (1 < cm1) ? 1 : cm1;
            int i2 = (2 < cm1) ? 2 : cm1;
            int i3 = (3 < cm1) ? 3 : cm1;
            float2 p0 = A2[__shfl_sync(0xffffffffu, kreg, 0)  * 32 + lane];
            float2 p1 = A2[__shfl_sync(0xffffffffu, kreg, i1) * 32 + lane];
            float2 p2 = A2[__shfl_sync(0xffffffffu, kreg, i2) * 32 + lane];
            float2 p3 = A2[__shfl_sync(0xffffffffu, kreg, i3) * 32 + lane];

            float* hb0 = hbuf[warp][0];
            float* hb1 = hbuf[warp][1];

#pragma unroll 1
            for (int n = 0; n < cnt; n += 2) {
                // prefetch samples n+4, n+5 (distance-2 iterations ahead)
                int j0 = (n + 4 < cnt) ? n + 4 : cm1;
                int j1 = (n + 5 < cnt) ? n + 5 : cm1;
                float2 q0 = A2[__shfl_sync(0xffffffffu, kreg, j0) * 32 + lane];
                float2 q1 = A2[__shfl_sync(0xffffffffu, kreg, j1) * 32 + lane];

                hb0[lane]      = fmaxf(fmaf(g1lo, p0.x - qlo, b1lo), 0.f);
                hb0[lane + 32] = fmaxf(fmaf(g1hi, p0.y - qhi, b1hi), 0.f);
                hb1[lane]      = fmaxf(fmaf(g1lo, p1.x - qlo, b1lo), 0.f);
                hb1[lane + 32] = fmaxf(fmaf(g1hi, p1.y - qhi, b1hi), 0.f);
                __syncwarp();

                ull a0 = 0, a1 = 0, c0 = 0, c1 = 0;      // sample n
                ull e0 = 0, e1 = 0, f0 = 0, f1 = 0;      // sample n+1
                const double2* h0 = (const double2*)hb0;
                const double2* h1 = (const double2*)hb1;
#pragma unroll
                for (int jj = 0; jj < 8; jj++) {
                    ull wl0 = w2lo[4 * jj + 0], wl1 = w2lo[4 * jj + 1];
                    ull wl2 = w2lo[4 * jj + 2], wl3 = w2lo[4 * jj + 3];
                    ull wh0 = w2hi[4 * jj + 0], wh1 = w2hi[4 * jj + 1];
                    ull wh2 = w2hi[4 * jj + 2], wh3 = w2hi[4 * jj + 3];
                    double2 v0 = h0[2 * jj], v1 = h0[2 * jj + 1];
                    double2 u0 = h1[2 * jj], u1 = h1[2 * jj + 1];
                    fma2(a0, d2u(v0.x), wl0); fma2(e0, d2u(u0.x), wl0);
                    fma2(a1, d2u(v0.y), wl1); fma2(e1, d2u(u0.y), wl1);
                    fma2(c0, d2u(v0.x), wh0); fma2(f0, d2u(u0.x), wh0);
                    fma2(c1, d2u(v0.y), wh1); fma2(f1, d2u(u0.y), wh1);
                    fma2(a0, d2u(v1.x), wl2); fma2(e0, d2u(u1.x), wl2);
                    fma2(a1, d2u(v1.y), wl3); fma2(e1, d2u(u1.y), wl3);
                    fma2(c0, d2u(v1.x), wh2); fma2(f0, d2u(u1.x), wh2);
                    fma2(c1, d2u(v1.y), wh3); fma2(f1, d2u(u1.y), wh3);
                }
                __syncwarp();

                float2 p, q2;
                p = unpack2(a0); q2 = unpack2(a1);
                mxA = fmaxf(mxA, fmaf(g2lo, (p.x + p.y) + (q2.x + q2.y), b2lo));
                p = unpack2(c0); q2 = unpack2(c1);
                mxB = fmaxf(mxB, fmaf(g2hi, (p.x + p.y) + (q2.x + q2.y), b2hi));
                p = unpack2(e0); q2 = unpack2(e1);
                mxA = fmaxf(mxA, fmaf(g2lo, (p.x + p.y) + (q2.x + q2.y), b2lo));
                p = unpack2(f0); q2 = unpack2(f1);
                mxB = fmaxf(mxB, fmaf(g2hi, (p.x + p.y) + (q2.x + q2.y), b2hi));

                p0 = p2; p1 = p3; p2 = q0; p3 = q1;
            }
            int ni = g / N_GRIDP, mi = g % N_GRIDP;
            int cpA = b * 64 + lane;
            d_perm[mi * 16384 + cpA * 128 + ni] = fmaxf(mxA, 0.f);
            d_perm[mi * 16384 + (cpA + 32) * 128 + ni] = fmaxf(mxB, 0.f);
        }
    }
}

// ---------------- k5: reduction GEMM layer1, split-K=36, f32x2 ----------------
__global__ void __launch_bounds__(256) k_red1(const float* __restrict__ W)
{
    __shared__ __align__(16) float As[32][132];
    __shared__ __align__(16) float Bs[32][68];
    const int ob = blockIdx.x * 64;
    const int kbase = blockIdx.y * KCHUNK;
    const int tid = threadIdx.x;
    const int tx = tid & 15, ty = tid >> 4;

    ull acc[4][4];
#pragma unroll
    for (int r = 0; r < 4; r++)
#pragma unroll
        for (int c = 0; c < 4; c++) acc[r][c] = 0;

    for (int kc = 0; kc < KCHUNK; kc += 32) {
        int k0 = kbase + kc;
#pragma unroll
        for (int r = 0; r < 16; r++) {
            int e = tid + 256 * r;
            int i = e >> 5, kk = e & 31;
            As[kk][i] = d_perm[i * K_RED + k0 + kk];
        }
#pragma unroll
        for (int r = 0; r < 8; r++) {
            int e = tid + 256 * r;
            int o = e >> 5, kk = e & 31;
            Bs[kk][o] = W[(ob + o) * K_RED + k0 + kk];
        }
        __syncthreads();
#pragma unroll
        for (int kk = 0; kk < 32; kk++) {
            double2 a01 = *(const double2*)&As[kk][ty * 8];
            double2 a23 = *(const double2*)&As[kk][ty * 8 + 4];
            float4 bv = *(const float4*)&Bs[kk][tx * 4];
            ull ap0 = d2u(a01.x), ap1 = d2u(a01.y), ap2 = d2u(a23.x), ap3 = d2u(a23.y);
            ull b0 = splat2(bv.x), b1 = splat2(bv.y), b2 = splat2(bv.z), b3 = splat2(bv.w);
            fma2(acc[0][0], ap0, b0); fma2(acc[0][1], ap0, b1); fma2(acc[0][2], ap0, b2); fma2(acc[0][3], ap0, b3);
            fma2(acc[1][0], ap1, b0); fma2(acc[1][1], ap1, b1); fma2(acc[1][2], ap1, b2); fma2(acc[1][3], ap1, b3);
            fma2(acc[2][0], ap2, b0); fma2(acc[2][1], ap2, b1); fma2(acc[2][2], ap2, b2); fma2(acc[2][3], ap2, b3);
            fma2(acc[3][0], ap3, b0); fma2(acc[3][1], ap3, b1); fma2(acc[3][2], ap3, b2); fma2(acc[3][3], ap3, b3);
        }
        __syncthreads();
    }
    float* outp = d_partial[blockIdx.y];
#pragma unroll
    for (int rp = 0; rp < 4; rp++)
#pragma unroll
        for (int c = 0; c < 4; c++) {
            float2 v = unpack2(acc[rp][c]);
            outp[(ty * 8 + 2 * rp) * 256 + ob + tx * 4 + c] = v.x;
            outp[(ty * 8 + 2 * rp + 1) * 256 + ob + tx * 4 + c] = v.y;
        }
}

// ---------------- k6: partial reduce + bias + relu ----------------
__global__ void k_redfin(const float* __restrict__ b1)
{
    int t = blockIdx.x * 256 + threadIdx.x;
    float s = b1[t & 255];
#pragma unroll
    for (int ks = 0; ks < KSPLIT; ks++) s += d_partial[ks][t];
    d_hbuf[t] = fmaxf(s, 0.f);
}

// ---------------- k6b: transpose W2 ----------------
__global__ void k_w2t(const float* __restrict__ W2)
{
    __shared__ float tbuf[32][33];
    int x = blockIdx.x * 32 + threadIdx.x;
    int y0 = blockIdx.y * 32;
#pragma unroll
    for (int r = threadIdx.y; r < 32; r += 8)
        tbuf[r][threadIdx.x] = W2[(y0 + r) * 256 + x];
    __syncthreads();
    int xo = blockIdx.y * 32 + threadIdx.x;
#pragma unroll
    for (int r = threadIdx.y; r < 32; r += 8)
        d_w2t[(blockIdx.x * 32 + r) * 256 + xo] = tbuf[threadIdx.x][r];
}

// ---------------- k7: layer2 256x256 + relu ----------------
__global__ void __launch_bounds__(256) k_red2(const float* __restrict__ b2, float* __restrict__ out)
{
    __shared__ float hs[256];
    int i = blockIdx.x;
    hs[threadIdx.x] = d_hbuf[i * 256 + threadIdx.x];
    __syncthreads();
    int o = threadIdx.x;
    float s = b2[o];
#pragma unroll 8
    for (int c = 0; c < 256; c++) s = fmaf(hs[c], d_w2t[c * 256 + o], s);
    out[i * 256 + o] = fmaxf(s, 0.f);
}

// ---------------- launch ----------------
extern "C" void kernel_launch(void* const* d_in, const int* in_sizes, int n_in,
                              void* d_out, int out_size)
{
    const float* wlh    = (const float*)d_in[0];
    const float* center = (const float*)d_in[1];
    const float* yaw    = (const float*)d_in[2];
    const float* u      = (const float*)d_in[3];
    const float* kp     = (const float*)d_in[4];
    const float* kf     = (const float*)d_in[5];
    const float* pn0_w1 = (const float*)d_in[6];
    const float* pn0_g1 = (const float*)d_in[7];
    const float* pn0_b1 = (const float*)d_in[8];
    const float* pn0_w2 = (const float*)d_in[9];
    const float* pn0_g2 = (const float*)d_in[10];
    const float* pn0_b2 = (const float*)d_in[11];
    const float* pn1_w1 = (const float*)d_in[12];
    const float* pn1_g1 = (const float*)d_in[13];
    const float* pn1_b1 = (const float*)d_in[14];
    const float* pn1_w2 = (const float*)d_in[15];
    const float* pn1_g2 = (const float*)d_in[16];
    const float* pn1_b2 = (const float*)d_in[17];
    const float* red_w1 = (const float*)d_in[18];
    const float* red_b1 = (const float*)d_in[19];
    const float* red_w2 = (const float*)d_in[20];
    const float* red_b2 = (const float*)d_in[21];
    float* out = (float*)d_out;

    cudaFuncSetAttribute(k_ball, cudaFuncAttributeMaxDynamicSharedMemorySize, 65536);
    cudaFuncSetAttribute(k_A,    cudaFuncAttributeMaxDynamicSharedMemorySize, 32768);

    k_grid<<<(G_TOT + 255) / 256, 256>>>(wlh, center, yaw, u);
    k_ball<<<G_TOT / 256, 256, 65536>>>(kp);
    k_A<<<dim3(64, 2), dim3(32, 8), 32768>>>(kp, kf, pn0_w1, pn1_w1);
    k_branch<<<148, 256>>>(pn0_w1, pn0_g1, pn0_b1, pn0_w2, pn0_g2, pn0_b2,
                           pn1_w1, pn1_g1, pn1_b1, pn1_w2, pn1_g2, pn1_b2);
    k_w2t<<<dim3(8, 8), dim3(32, 8)>>>(red_w2);
    k_red1<<<dim3(4, KSPLIT), 256>>>(red_w1);
    k_redfin<<<128, 256>>>(red_b1);
    k_red2<<<128, 256>>>(red_b2, out);
}

// round 11
// speedup vs baseline: 3.3737x; 1.1105x over previous
#include <cuda_runtime.h>
#include <cuda_bf16.h>

#define N_PROP 128
#define N_GRIDP 216
#define G_TOT  27648
#define N_KEY  4096
#define C_FEAT 128
#define NS     16
#define K_RED  27648
#define KSPLIT 36
#define KCHUNK 768
#define NCHUNK 3456              // 2 * 27648 / 16
#define BQ_THREADS 512

typedef unsigned long long ull;

// ---------------- scratch ----------------
static __device__ float  d_grid[G_TOT * 3];
static __device__ float2 d_A[2][N_KEY * 32];
static __device__ int    d_idx[2][G_TOT * NS];
static __device__ int    d_cnt[2][G_TOT];
static __device__ float  d_perm[N_PROP * K_RED];
static __device__ float  d_partial[KSPLIT][N_PROP * 256];
static __device__ float  d_hbuf[N_PROP * 256];
static __device__ float  d_w2t[256 * 256];
static __device__ unsigned d_work;

// ---------------- f32x2 helpers ----------------
__device__ __forceinline__ ull splat2(float x) {
    ull r;
    asm("mov.b64 %0, {%1, %1};" : "=l"(r) : "f"(x));
    return r;
}
__device__ __forceinline__ void fma2(ull& acc, ull a, ull b) {
    asm("fma.rn.f32x2 %0, %1, %2, %0;" : "+l"(acc) : "l"(a), "l"(b));
}
__device__ __forceinline__ float2 unpack2(ull v) {
    float lo, hi;
    asm("mov.b64 {%0, %1}, %2;" : "=f"(lo), "=f"(hi) : "l"(v));
    return make_float2(lo, hi);
}
__device__ __forceinline__ ull d2u(double d) { return __double_as_longlong(d); }

// ---------------- k1: grid points (+ work counter reset) ----------------
__global__ void k_grid(const float* __restrict__ wlh, const float* __restrict__ center,
                       const float* __restrict__ yaw, const float* __restrict__ u)
{
    if (blockIdx.x == 0 && threadIdx.x == 0) d_work = 0u;
    int g = blockIdx.x * 256 + threadIdx.x;
    if (g >= G_TOT) return;
    int ni = g / N_GRIDP;
    float gx = u[g * 3 + 0] * wlh[ni * 3 + 0];
    float gy = u[g * 3 + 1] * wlh[ni * 3 + 1];
    float gz = u[g * 3 + 2] * wlh[ni * 3 + 2];
    float yv = yaw[ni];
    float c = cosf(yv), s = sinf(yv);
    float rx = c * gx - s * gy;
    float ry = s * gx + c * gy;
    d_grid[g * 3 + 0] = rx + center[ni * 3 + 0];
    d_grid[g * 3 + 1] = ry + center[ni * 3 + 1];
    d_grid[g * 3 + 2] = gz + center[ni * 3 + 2];
}

// ---------------- k2: per-keypoint A, kf staged coalesced in smem ----------------
__global__ void __launch_bounds__(256) k_A(const float* __restrict__ kp, const float* __restrict__ kf,
                                           const float* __restrict__ w1_0, const float* __restrict__ w1_1)
{
    __shared__ float w1s[64 * 131];
    extern __shared__ float kfs[];            // 128 c x 64 k = 32 KB dynamic
    const float* w1 = blockIdx.y ? w1_1 : w1_0;
    int tid = threadIdx.y * 32 + threadIdx.x;
    for (int i = tid; i < 64 * 131; i += 256) w1s[i] = w1[i];

    int kbase = blockIdx.x * 64;
    for (int e = tid; e < C_FEAT * 64; e += 256) {
        int c = e >> 6, kk = e & 63;
        kfs[c * 64 + kk] = kf[c * N_KEY + kbase + kk];
    }
    __syncthreads();

    int l = threadIdx.x;
#pragma unroll 1
    for (int t = 0; t < 8; t++) {
        int kk = t * 8 + threadIdx.y;
        int k = kbase + kk;
        float kx = kp[k * 3 + 0], ky = kp[k * 3 + 1], kz = kp[k * 3 + 2];
        float a0 = w1s[l * 131 + 0] * kx + w1s[l * 131 + 1] * ky + w1s[l * 131 + 2] * kz;
        float a1 = w1s[(l + 32) * 131 + 0] * kx + w1s[(l + 32) * 131 + 1] * ky + w1s[(l + 32) * 131 + 2] * kz;
#pragma unroll 4
        for (int c = 0; c < C_FEAT; c++) {
            float f = kfs[c * 64 + kk];
            a0 = fmaf(f, w1s[l * 131 + 3 + c], a0);
            a1 = fmaf(f, w1s[(l + 32) * 131 + 3 + c], a1);
        }
        d_A[blockIdx.y][k * 32 + l] = make_float2(a0, a1);
    }
}

// ---------------- k3: warp-cooperative ball query ----------------
// One warp per grid point; lane l scans keys [128l, 128l+128).
// Lane-local first-16 hits, then warp prefix-scan merge -> globally-first-16
// in ascending-k order (identical to reference semantics).
__device__ __forceinline__ void bq_merge(int* __restrict__ out, int* __restrict__ cntout,
                                         int c, const int* h, int lane)
{
    const unsigned full = 0xffffffffu;
    int pre = c;
#pragma unroll
    for (int off = 1; off < 32; off <<= 1) {
        int t = __shfl_up_sync(full, pre, off);
        if (lane >= off) pre += t;
    }
    int excl = pre - c;
    int total = __shfl_sync(full, pre, 31);
    unsigned ball = __ballot_sync(full, c > 0);
    int myfirst = lane * 128 + h[0];
    int fl = (ball != 0u) ? (__ffs(ball) - 1) : 0;
    int f = __shfl_sync(full, myfirst, fl);
    if (ball == 0u) f = 0;
#pragma unroll 1
    for (int t = 0; t < c; t++) {
        int pos = excl + t;
        if (pos < NS) out[pos] = lane * 128 + h[t];
    }
    int tot16 = (total < NS) ? total : NS;
    for (int p = tot16 + lane; p < NS; p += 32) out[p] = f;
    if (lane == 0) *cntout = (tot16 > 0) ? tot16 : 1;
}

__global__ void __launch_bounds__(BQ_THREADS) k_ball(const float* __restrict__ kp)
{
    extern __shared__ float4 kpt[];   // [lane*129 + i], 4128 float4 = 66048 B
    int tid = threadIdx.x;
    for (int k = tid; k < N_KEY; k += BQ_THREADS) {
        int l = k >> 7, i = k & 127;
        float kx = kp[k * 3 + 0], ky = kp[k * 3 + 1], kz = kp[k * 3 + 2];
        kpt[l * 129 + i] = make_float4(kx, ky, kz, kx * kx + ky * ky + kz * kz);
    }
    __syncthreads();

    int lane = tid & 31, warp = tid >> 5;
    int g = blockIdx.x * (BQ_THREADS / 32) + warp;

    float gx = d_grid[g * 3 + 0], gy = d_grid[g * 3 + 1], gz = d_grid[g * 3 + 2];
    float gs = gx * gx + gy * gy + gz * gz;
    float m2x = -2.f * gx, m2y = -2.f * gy, m2z = -2.f * gz;

    int h0[NS], h1[NS];
    h0[0] = 0; h1[0] = 0;
    int c0 = 0, c1 = 0;
    const float4* my = kpt + lane * 129;

#pragma unroll 1
    for (int i = 0; i < 128; i += 4) {
        float4 v0 = my[i + 0];
        float4 v1 = my[i + 1];
        float4 v2 = my[i + 2];
        float4 v3 = my[i + 3];
        float d20 = fmaf(m2x, v0.x, fmaf(m2y, v0.y, fmaf(m2z, v0.z, gs + v0.w)));
        float d21 = fmaf(m2x, v1.x, fmaf(m2y, v1.y, fmaf(m2z, v1.z, gs + v1.w)));
        float d22 = fmaf(m2x, v2.x, fmaf(m2y, v2.y, fmaf(m2z, v2.z, gs + v2.w)));
        float d23 = fmaf(m2x, v3.x, fmaf(m2y, v3.y, fmaf(m2z, v3.z, gs + v3.w)));
        if (fminf(fminf(d20, d21), fminf(d22, d23)) < 2.56f) {   // rare
            if (d20 < 2.56f) { if (c1 < NS) h1[c1++] = i + 0; if (d20 < 0.64f && c0 < NS) h0[c0++] = i + 0; }
            if (d21 < 2.56f) { if (c1 < NS) h1[c1++] = i + 1; if (d21 < 0.64f && c0 < NS) h0[c0++] = i + 1; }
            if (d22 < 2.56f) { if (c1 < NS) h1[c1++] = i + 2; if (d22 < 0.64f && c0 < NS) h0[c0++] = i + 2; }
            if (d23 < 2.56f) { if (c1 < NS) h1[c1++] = i + 3; if (d23 < 0.64f && c0 < NS) h0[c0++] = i + 3; }
        }
    }
    bq_merge(&d_idx[0][g * NS], &d_cnt[0][g], c0, h0, lane);
    bq_merge(&d_idx[1][g * NS], &d_cnt[1][g], c1, h1, lane);
}

// ---------------- k4: branch MLP + maxpool, 4-buffer rotation ----------
__global__ void __launch_bounds__(256, 1) k_branch(
    const float* __restrict__ w1_0, const float* __restrict__ g1_0, const float* __restrict__ b1_0,
    const float* __restrict__ w2_0, const float* __restrict__ g2_0, const float* __restrict__ b2_0,
    const float* __restrict__ w1_1, const float* __restrict__ g1_1, const float* __restrict__ b1_1,
    const float* __restrict__ w2_1, const float* __restrict__ g2_1, const float* __restrict__ b2_1)
{
    const int lane = threadIdx.x & 31;
    const int warp = threadIdx.x >> 5;
    const int tid  = threadIdx.x;

    __shared__ __align__(16) float hbuf[8][4][64];   // 4 rotating buffers per warp
    __shared__ int s_chunk;

    int cur_b = -1;
    ull w2lo[32], w2hi[32];
    float g1lo = 0, g1hi = 0, b1lo = 0, b1hi = 0, g2lo = 0, g2hi = 0, b2lo = 0, b2hi = 0;
    float w1x0 = 0, w1y0 = 0, w1z0 = 0, w1x1 = 0, w1y1 = 0, w1z1 = 0;
    const float2* A2 = d_A[0];
    const int*    idxp = d_idx[0];
    const int*    cntp = d_cnt[0];

    for (;;) {
        __syncthreads();
        if (tid == 0) s_chunk = (int)atomicAdd(&d_work, 1u);
        __syncthreads();
        int chunk = s_chunk;
        if (chunk >= NCHUNK) break;

        int b = (chunk >= NCHUNK / 2);
        int gbase = (chunk - b * (NCHUNK / 2)) * 16;

        if (b != cur_b) {
            cur_b = b;
            const float* w1 = b ? w1_1 : w1_0;
            const float* g1 = b ? g1_1 : g1_0;
            const float* b1 = b ? b1_1 : b1_0;
            const float* w2 = b ? w2_1 : w2_0;
            const float* g2 = b ? g2_1 : g2_0;
            const float* b2 = b ? b2_1 : b2_0;
            const double2* w2d = (const double2*)w2;
#pragma unroll
            for (int jj = 0; jj < 16; jj++) {
                double2 vlo = w2d[lane * 16 + jj];
                double2 vhi = w2d[(lane + 32) * 16 + jj];
                w2lo[2 * jj] = d2u(vlo.x); w2lo[2 * jj + 1] = d2u(vlo.y);
                w2hi[2 * jj] = d2u(vhi.x); w2hi[2 * jj + 1] = d2u(vhi.y);
            }
            g1lo = g1[lane]; g1hi = g1[lane + 32];
            b1lo = b1[lane]; b1hi = b1[lane + 32];
            g2lo = g2[lane]; g2hi = g2[lane + 32];
            b2lo = b2[lane]; b2hi = b2[lane + 32];
            w1x0 = w1[lane * 131 + 0]; w1y0 = w1[lane * 131 + 1]; w1z0 = w1[lane * 131 + 2];
            w1x1 = w1[(lane + 32) * 131 + 0]; w1y1 = w1[(lane + 32) * 131 + 1]; w1z1 = w1[(lane + 32) * 131 + 2];
            A2 = d_A[b];
            idxp = d_idx[b];
            cntp = d_cnt[b];
        }

#pragma unroll 1
        for (int gi = 0; gi < 2; gi++) {
            int g = gbase + warp * 2 + gi;
            float gx = d_grid[g * 3 + 0], gy = d_grid[g * 3 + 1], gz = d_grid[g * 3 + 2];
            float qlo = w1x0 * gx + w1y0 * gy + w1z0 * gz;
            float qhi = w1x1 * gx + w1y1 * gy + w1z1 * gz;
            int cnt = cntp[g];
            int cm1 = cnt - 1;
            int kreg = idxp[g * NS + (lane & 15)];
            float mxA = -1e30f, mxB = -1e30f;

            int i1 = (1 < cm1) ? 1 : cm1;
            int i2 = (2 < cm1) ? 2 : cm1;
            int i3 = (3 < cm1) ? 3 : cm1;
            float2 p0 = A2[__shfl_sync(0xffffffffu, kreg, 0)  * 32 + lane];
            float2 p1 = A2[__shfl_sync(0xffffffffu, kreg, i1) * 32 + lane];
            float2 p2 = A2[__shfl_sync(0xffffffffu, kreg, i2) * 32 + lane];
            float2 p3 = A2[__shfl_sync(0xffffffffu, kreg, i3) * 32 + lane];

#pragma unroll 1
            for (int n = 0; n < cnt; n += 2) {
                int j0 = (n + 4 < cnt) ? n + 4 : cm1;
                int j1 = (n + 5 < cnt) ? n + 5 : cm1;
                float2 q0 = A2[__shfl_sync(0xffffffffu, kreg, j0) * 32 + lane];
                float2 q1 = A2[__shfl_sync(0xffffffffu, kreg, j1) * 32 + lane];

                float* hb0 = hbuf[warp][((n >> 1) & 1) * 2 + 0];
                float* hb1 = hbuf[warp][((n >> 1) & 1) * 2 + 1];
                hb0[lane]      = fmaxf(fmaf(g1lo, p0.x - qlo, b1lo), 0.f);
                hb0[lane + 32] = fmaxf(fmaf(g1hi, p0.y - qhi, b1hi), 0.f);
                hb1[lane]      = fmaxf(fmaf(g1lo, p1.x - qlo, b1lo), 0.f);
                hb1[lane + 32] = fmaxf(fmaf(g1hi, p1.y - qhi, b1hi), 0.f);
                __syncwarp();

                ull a0 = 0, a1 = 0, c0 = 0, c1 = 0;      // sample n
                ull e0 = 0, e1 = 0, f0 = 0, f1 = 0;      // sample n+1
                const double2* h0 = (const double2*)hb0;
                const double2* h1 = (const double2*)hb1;
#pragma unroll
                for (int jj = 0; jj < 8; jj++) {
                    ull wl0 = w2lo[4 * jj + 0], wl1 = w2lo[4 * jj + 1];
                    ull wl2 = w2lo[4 * jj + 2], wl3 = w2lo[4 * jj + 3];
                    ull wh0 = w2hi[4 * jj + 0], wh1 = w2hi[4 * jj + 1];
                    ull wh2 = w2hi[4 * jj + 2], wh3 = w2hi[4 * jj + 3];
                    double2 v0 = h0[2 * jj], v1 = h0[2 * jj + 1];
                    double2 u0 = h1[2 * jj], u1 = h1[2 * jj + 1];
                    fma2(a0, d2u(v0.x), wl0); fma2(e0, d2u(u0.x), wl0);
                    fma2(a1, d2u(v0.y), wl1); fma2(e1, d2u(u0.y), wl1);
                    fma2(c0, d2u(v0.x), wh0); fma2(f0, d2u(u0.x), wh0);
                    fma2(c1, d2u(v0.y), wh1); fma2(f1, d2u(u0.y), wh1);
                    fma2(a0, d2u(v1.x), wl2); fma2(e0, d2u(u1.x), wl2);
                    fma2(a1, d2u(v1.y), wl3); fma2(e1, d2u(u1.y), wl3);
                    fma2(c0, d2u(v1.x), wh2); fma2(f0, d2u(u1.x), wh2);
                    fma2(c1, d2u(v1.y), wh3); fma2(f1, d2u(u1.y), wh3);
                }

                float2 p, q2;
                p = unpack2(a0); q2 = unpack2(a1);
                mxA = fmaxf(mxA, fmaf(g2lo, (p.x + p.y) + (q2.x + q2.y), b2lo));
                p = unpack2(c0); q2 = unpack2(c1);
                mxB = fmaxf(mxB, fmaf(g2hi, (p.x + p.y) + (q2.x + q2.y), b2hi));
                p = unpack2(e0); q2 = unpack2(e1);
                mxA = fmaxf(mxA, fmaf(g2lo, (p.x + p.y) + (q2.x + q2.y), b2lo));
                p = unpack2(f0); q2 = unpack2(f1);
                mxB = fmaxf(mxB, fmaf(g2hi, (p.x + p.y) + (q2.x + q2.y), b2hi));

                p0 = p2; p1 = p3; p2 = q0; p3 = q1;
            }
            int ni = g / N_GRIDP, mi = g % N_GRIDP;
            int cpA = b * 64 + lane;
            d_perm[mi * 16384 + cpA * 128 + ni] = fmaxf(mxA, 0.f);
            d_perm[mi * 16384 + (cpA + 32) * 128 + ni] = fmaxf(mxB, 0.f);
        }
    }
}

// ---------------- k5: reduction GEMM layer1, split-K=36, f32x2 ----------------
__global__ void __launch_bounds__(256) k_red1(const float* __restrict__ W)
{
    __shared__ __align__(16) float As[32][132];
    __shared__ __align__(16) float Bs[32][68];
    const int ob = blockIdx.x * 64;
    const int kbase = blockIdx.y * KCHUNK;
    const int tid = threadIdx.x;
    const int tx = tid & 15, ty = tid >> 4;

    ull acc[4][4];
#pragma unroll
    for (int r = 0; r < 4; r++)
#pragma unroll
        for (int c = 0; c < 4; c++) acc[r][c] = 0;

    for (int kc = 0; kc < KCHUNK; kc += 32) {
        int k0 = kbase + kc;
#pragma unroll
        for (int r = 0; r < 16; r++) {
            int e = tid + 256 * r;
            int i = e >> 5, kk = e & 31;
            As[kk][i] = d_perm[i * K_RED + k0 + kk];
        }
#pragma unroll
        for (int r = 0; r < 8; r++) {
            int e = tid + 256 * r;
            int o = e >> 5, kk = e & 31;
            Bs[kk][o] = W[(ob + o) * K_RED + k0 + kk];
        }
        __syncthreads();
#pragma unroll
        for (int kk = 0; kk < 32; kk++) {
            double2 a01 = *(const double2*)&As[kk][ty * 8];
            double2 a23 = *(const double2*)&As[kk][ty * 8 + 4];
            float4 bv = *(const float4*)&Bs[kk][tx * 4];
            ull ap0 = d2u(a01.x), ap1 = d2u(a01.y), ap2 = d2u(a23.x), ap3 = d2u(a23.y);
            ull b0 = splat2(bv.x), b1 = splat2(bv.y), b2 = splat2(bv.z), b3 = splat2(bv.w);
            fma2(acc[0][0], ap0, b0); fma2(acc[0][1], ap0, b1); fma2(acc[0][2], ap0, b2); fma2(acc[0][3], ap0, b3);
            fma2(acc[1][0], ap1, b0); fma2(acc[1][1], ap1, b1); fma2(acc[1][2], ap1, b2); fma2(acc[1][3], ap1, b3);
            fma2(acc[2][0], ap2, b0); fma2(acc[2][1], ap2, b1); fma2(acc[2][2], ap2, b2); fma2(acc[2][3], ap2, b3);
            fma2(acc[3][0], ap3, b0); fma2(acc[3][1], ap3, b1); fma2(acc[3][2], ap3, b2); fma2(acc[3][3], ap3, b3);
        }
        __syncthreads();
    }
    float* outp = d_partial[blockIdx.y];
#pragma unroll
    for (int rp = 0; rp < 4; rp++)
#pragma unroll
        for (int c = 0; c < 4; c++) {
            float2 v = unpack2(acc[rp][c]);
            outp[(ty * 8 + 2 * rp) * 256 + ob + tx * 4 + c] = v.x;
            outp[(ty * 8 + 2 * rp + 1) * 256 + ob + tx * 4 + c] = v.y;
        }
}

// ---------------- k6: partial reduce + bias + relu ----------------
__global__ void k_redfin(const float* __restrict__ b1)
{
    int t = blockIdx.x * 256 + threadIdx.x;
    float s = b1[t & 255];
#pragma unroll
    for (int ks = 0; ks < KSPLIT; ks++) s += d_partial[ks][t];
    d_hbuf[t] = fmaxf(s, 0.f);
}

// ---------------- k6b: transpose W2 ----------------
__global__ void k_w2t(const float* __restrict__ W2)
{
    __shared__ float tbuf[32][33];
    int x = blockIdx.x * 32 + threadIdx.x;
    int y0 = blockIdx.y * 32;
#pragma unroll
    for (int r = threadIdx.y; r < 32; r += 8)
        tbuf[r][threadIdx.x] = W2[(y0 + r) * 256 + x];
    __syncthreads();
    int xo = blockIdx.y * 32 + threadIdx.x;
#pragma unroll
    for (int r = threadIdx.y; r < 32; r += 8)
        d_w2t[(blockIdx.x * 32 + r) * 256 + xo] = tbuf[threadIdx.x][r];
}

// ---------------- k7: layer2 256x256 + relu ----------------
__global__ void __launch_bounds__(256) k_red2(const float* __restrict__ b2, float* __restrict__ out)
{
    __shared__ float hs[256];
    int i = blockIdx.x;
    hs[threadIdx.x] = d_hbuf[i * 256 + threadIdx.x];
    __syncthreads();
    int o = threadIdx.x;
    float s = b2[o];
#pragma unroll 8
    for (int c = 0; c < 256; c++) s = fmaf(hs[c], d_w2t[c * 256 + o], s);
    out[i * 256 + o] = fmaxf(s, 0.f);
}

// ---------------- launch ----------------
extern "C" void kernel_launch(void* const* d_in, const int* in_sizes, int n_in,
                              void* d_out, int out_size)
{
    const float* wlh    = (const float*)d_in[0];
    const float* center = (const float*)d_in[1];
    const float* yaw    = (const float*)d_in[2];
    const float* u      = (const float*)d_in[3];
    const float* kp     = (const float*)d_in[4];
    const float* kf     = (const float*)d_in[5];
    const float* pn0_w1 = (const float*)d_in[6];
    const float* pn0_g1 = (const float*)d_in[7];
    const float* pn0_b1 = (const float*)d_in[8];
    const float* pn0_w2 = (const float*)d_in[9];
    const float* pn0_g2 = (const float*)d_in[10];
    const float* pn0_b2 = (const float*)d_in[11];
    const float* pn1_w1 = (const float*)d_in[12];
    const float* pn1_g1 = (const float*)d_in[13];
    const float* pn1_b1 = (const float*)d_in[14];
    const float* pn1_w2 = (const float*)d_in[15];
    const float* pn1_g2 = (const float*)d_in[16];
    const float* pn1_b2 = (const float*)d_in[17];
    const float* red_w1 = (const float*)d_in[18];
    const float* red_b1 = (const float*)d_in[19];
    const float* red_w2 = (const float*)d_in[20];
    const float* red_b2 = (const float*)d_in[21];
    float* out = (float*)d_out;

    cudaFuncSetAttribute(k_ball, cudaFuncAttributeMaxDynamicSharedMemorySize, 66048);
    cudaFuncSetAttribute(k_A,    cudaFuncAttributeMaxDynamicSharedMemorySize, 32768);

    k_grid<<<(G_TOT + 255) / 256, 256>>>(wlh, center, yaw, u);
    k_ball<<<G_TOT / (BQ_THREADS / 32), BQ_THREADS, 66048>>>(kp);
    k_A<<<dim3(64, 2), dim3(32, 8), 32768>>>(kp, kf, pn0_w1, pn1_w1);
    k_branch<<<148, 256>>>(pn0_w1, pn0_g1, pn0_b1, pn0_w2, pn0_g2, pn0_b2,
                           pn1_w1, pn1_g1, pn1_b1, pn1_w2, pn1_g2, pn1_b2);
    k_w2t<<<dim3(8, 8), dim3(32, 8)>>>(red_w2);
    k_red1<<<dim3(4, KSPLIT), 256>>>(red_w1);
    k_redfin<<<128, 256>>>(red_b1);
    k_red2<<<128, 256>>>(red_b2, out);
}